// round 1
// baseline (speedup 1.0000x reference)
#include <cuda_runtime.h>
#include <math.h>

// ---------------- problem dims ----------------
#define B_      2
#define S_      2048
#define DM      2048
#define NH      16
#define DNOPE   128
#define DROPE   64
#define DQKD    192           // DNOPE + DROPE
#define DKVL    512
#define DV      128
#define BS      (B_*S_)       // 4096
#define HQ      (NH*DQKD)     // 3072
#define HKV     (NH*(DNOPE+DV)) // 4096
#define KVA_N   (DKVL+DROPE)  // 576
#define RMS_EPS 1.1920928955078125e-07f
// log(10000)/32
#define ROPE_LC 0.28782313662425572f

// ---------------- scratch (no allocations allowed) ----------------
__device__ float g_q  [BS*HQ];      // q projections (rope applied in place)
__device__ float g_kva[BS*KVA_N];   // x @ Wkv_a
__device__ float g_ckv[BS*DKVL];    // rmsnormed c_kv
__device__ float g_kr [BS*DROPE];   // rope'd k_rope (shared across heads)
__device__ float g_kvb[BS*HKV];     // c_kv @ Wkv_b : per head 128 k_nope + 128 v
__device__ float g_att[BS*(NH*DV)]; // attention output

// ---------------- generic fp32 SGEMM: C[M,N] = A[M,K] @ B[K,N] ----------------
// 128x128 tile, K-step 8, 256 threads, 8x8 per-thread micro-tile.
// Requirements used here: M % 128 == 0, K % 8 == 0, N % 4 == 0 (N guarded).
__global__ void __launch_bounds__(256, 2)
sgemm128(const float* __restrict__ A, const float* __restrict__ Bm,
         float* __restrict__ C, int M, int N, int K)
{
    __shared__ float As[8][128];
    __shared__ float Bs[8][128];

    const int tid = threadIdx.x;
    const int ty  = tid >> 4;        // 0..15
    const int tx  = tid & 15;        // 0..15
    const int m0  = blockIdx.y * 128;
    const int n0  = blockIdx.x * 128;

    const int ar = tid >> 1;         // 0..127
    const int ac = (tid & 1) * 4;    // 0 or 4
    const int br = tid >> 5;         // 0..7
    const int bc = (tid & 31) * 4;   // 0..124

    float acc[8][8];
#pragma unroll
    for (int i = 0; i < 8; i++)
#pragma unroll
        for (int j = 0; j < 8; j++) acc[i][j] = 0.f;

    for (int k0 = 0; k0 < K; k0 += 8) {
        // A tile (transposed into smem)
        float4 av = *(const float4*)&A[(size_t)(m0 + ar) * K + k0 + ac];
        As[ac + 0][ar] = av.x;
        As[ac + 1][ar] = av.y;
        As[ac + 2][ar] = av.z;
        As[ac + 3][ar] = av.w;
        // B tile
        float4 bv;
        if (n0 + bc < N) bv = *(const float4*)&Bm[(size_t)(k0 + br) * N + n0 + bc];
        else             bv = make_float4(0.f, 0.f, 0.f, 0.f);
        *(float4*)&Bs[br][bc] = bv;
        __syncthreads();

#pragma unroll
        for (int kk = 0; kk < 8; kk++) {
            float a[8], b[8];
            *(float4*)&a[0] = *(const float4*)&As[kk][ty * 8];
            *(float4*)&a[4] = *(const float4*)&As[kk][ty * 8 + 4];
            *(float4*)&b[0] = *(const float4*)&Bs[kk][tx * 8];
            *(float4*)&b[4] = *(const float4*)&Bs[kk][tx * 8 + 4];
#pragma unroll
            for (int i = 0; i < 8; i++)
#pragma unroll
                for (int j = 0; j < 8; j++)
                    acc[i][j] = fmaf(a[i], b[j], acc[i][j]);
        }
        __syncthreads();
    }

#pragma unroll
    for (int i = 0; i < 8; i++) {
        const int row = m0 + ty * 8 + i;
#pragma unroll
        for (int j = 0; j < 8; j += 4) {
            const int col = n0 + tx * 8 + j;
            if (col < N)
                *(float4*)&C[(size_t)row * N + col] =
                    make_float4(acc[i][j], acc[i][j+1], acc[i][j+2], acc[i][j+3]);
        }
    }
}

// ---------------- prep: RMSNorm(c_kv), RoPE(k_rope), RoPE(q_rope in place) ----
// one block per (b*s) row, 256 threads.
__global__ void prep_kernel(const float* __restrict__ w)
{
    const int row = blockIdx.x;
    const int s   = row % S_;
    const int tid = threadIdx.x;

    // ---- RMSNorm over c_kv (512) ----
    const float c0 = g_kva[(size_t)row * KVA_N + tid];
    const float c1 = g_kva[(size_t)row * KVA_N + tid + 256];
    float ss = c0 * c0 + c1 * c1;
#pragma unroll
    for (int o = 16; o > 0; o >>= 1) ss += __shfl_xor_sync(0xffffffffu, ss, o);
    __shared__ float red[8];
    if ((tid & 31) == 0) red[tid >> 5] = ss;
    __syncthreads();
    if (tid == 0) {
        float v = 0.f;
#pragma unroll
        for (int i = 0; i < 8; i++) v += red[i];
        red[0] = v;
    }
    __syncthreads();
    const float inv = rsqrtf(red[0] * (1.f / 512.f) + RMS_EPS);
    g_ckv[(size_t)row * DKVL + tid]       = c0 * inv * w[tid];
    g_ckv[(size_t)row * DKVL + tid + 256] = c1 * inv * w[tid + 256];

    // ---- RoPE k_rope (32 pairs) ----
    if (tid < 32) {
        const float fr = expf(-(float)tid * ROPE_LC);
        const float t  = (float)s * fr;
        const float cs = cosf(t), sn = sinf(t);
        const float x1 = g_kva[(size_t)row * KVA_N + DKVL + 2 * tid];
        const float x2 = g_kva[(size_t)row * KVA_N + DKVL + 2 * tid + 1];
        g_kr[(size_t)row * DROPE + 2 * tid]     = x1 * cs - x2 * sn;
        g_kr[(size_t)row * DROPE + 2 * tid + 1] = x2 * cs + x1 * sn;
    }

    // ---- RoPE q (16 heads x 32 pairs, in place) ----
    for (int p = tid; p < NH * 32; p += 256) {
        const int h = p >> 5, i = p & 31;
        const float fr = expf(-(float)i * ROPE_LC);
        const float t  = (float)s * fr;
        const float cs = cosf(t), sn = sinf(t);
        const size_t base = (size_t)row * HQ + h * DQKD + DNOPE + 2 * i;
        const float x1 = g_q[base], x2 = g_q[base + 1];
        g_q[base]     = x1 * cs - x2 * sn;
        g_q[base + 1] = x2 * cs + x1 * sn;
    }
}

// ---------------- causal flash attention ----------------
// grid (S/64, NH, B), 256 threads. BM = BN = 64. fp32 online softmax.
#define AT_BM 64
#define AT_BN 64
#define SSTR  68   // padded row stride for Qs/Ks/Ss (words)

#define ATT_SMEM_FLOATS (DQKD*SSTR /*Qs*/ + DQKD*SSTR /*Ks*/ + AT_BM*SSTR /*Ss*/ + AT_BN*DV /*Vs*/ + 3*AT_BM)
#define ATT_SMEM_BYTES  (ATT_SMEM_FLOATS * 4)

__global__ void attn_kernel()
{
    extern __shared__ float sm[];
    float* Qs   = sm;                       // [192][68] (d-major)
    float* Ks   = Qs + DQKD * SSTR;         // [192][68]
    float* Ss   = Ks + DQKD * SSTR;         // [64][68]
    float* Vs   = Ss + AT_BM * SSTR;        // [64][128]
    float* rowm = Vs + AT_BN * DV;          // [64]
    float* rowl = rowm + AT_BM;             // [64]
    float* rowa = rowl + AT_BM;             // [64]

    const int qblk = blockIdx.x;
    const int h    = blockIdx.y;
    const int b    = blockIdx.z;
    const int tid  = threadIdx.x;
    const int ti   = tid >> 4;   // 0..15 (score rows /4)
    const int tj   = tid & 15;   // 0..15 (score cols /4)
    const int ro   = tid >> 2;   // 0..63 (output row)
    const int cg   = tid & 3;    // 0..3  (output col group of 32)

    const float scale = 0.07216878364870323f; // 1/sqrt(192)
    const int q0 = qblk * AT_BM;

    // load Q tile (d-major, padded)
    for (int e = tid; e < AT_BM * DQKD; e += 256) {
        const int r = e / DQKD, d = e % DQKD;
        Qs[d * SSTR + r] = g_q[(size_t)(b * S_ + q0 + r) * HQ + h * DQKD + d];
    }
    if (tid < AT_BM) { rowm[tid] = -1e30f; rowl[tid] = 0.f; }

    float o[32];
#pragma unroll
    for (int u = 0; u < 32; u++) o[u] = 0.f;
    __syncthreads();

    for (int kt = 0; kt <= qblk; kt++) {
        const int k0 = kt * AT_BN;

        // load K tile (nope part from kvb, rope part broadcast) and V tile
        for (int e = tid; e < AT_BN * DQKD; e += 256) {
            const int j = e / DQKD, d = e % DQKD;
            float v;
            if (d < DNOPE)
                v = g_kvb[(size_t)(b * S_ + k0 + j) * HKV + h * (DNOPE + DV) + d];
            else
                v = g_kr[(size_t)(b * S_ + k0 + j) * DROPE + (d - DNOPE)];
            Ks[d * SSTR + j] = v;
        }
        for (int e = tid; e < AT_BN * DV; e += 256) {
            const int j = e >> 7, c = e & 127;
            Vs[j * DV + c] = g_kvb[(size_t)(b * S_ + k0 + j) * HKV + h * (DNOPE + DV) + DNOPE + c];
        }
        __syncthreads();

        // ---- scores: 4x4 micro-tile per thread over K=192 ----
        float acc[4][4];
#pragma unroll
        for (int i = 0; i < 4; i++)
#pragma unroll
            for (int j = 0; j < 4; j++) acc[i][j] = 0.f;

        for (int kk = 0; kk < DQKD; kk++) {
            const float4 a4 = *(const float4*)&Qs[kk * SSTR + ti * 4];
            const float4 b4 = *(const float4*)&Ks[kk * SSTR + tj * 4];
            const float av[4] = {a4.x, a4.y, a4.z, a4.w};
            const float bv[4] = {b4.x, b4.y, b4.z, b4.w};
#pragma unroll
            for (int i = 0; i < 4; i++)
#pragma unroll
                for (int j = 0; j < 4; j++)
                    acc[i][j] = fmaf(av[i], bv[j], acc[i][j]);
        }

        const bool diag = (kt == qblk);
#pragma unroll
        for (int i = 0; i < 4; i++) {
            const int qi = q0 + ti * 4 + i;
#pragma unroll
            for (int j = 0; j < 4; j++) {
                const int kj = k0 + tj * 4 + j;
                float sv = acc[i][j] * scale;
                if (diag && kj > qi) sv = -1e30f;
                acc[i][j] = sv;
                Ss[(ti * 4 + i) * SSTR + tj * 4 + j] = sv;
            }
        }
        __syncthreads();

        // ---- stats 1: new row max + rescale factor ----
        if (tid < AT_BM) {
            const float* srow = &Ss[tid * SSTR];
            float mt = -1e30f;
#pragma unroll 8
            for (int j = 0; j < AT_BN; j++) mt = fmaxf(mt, srow[j]);
            const float m  = rowm[tid];
            const float mn = fmaxf(m, mt);
            rowa[tid] = __expf(m - mn);
            rowm[tid] = mn;
        }
        __syncthreads();

        // ---- exp transform (from registers) ----
#pragma unroll
        for (int i = 0; i < 4; i++) {
            const float mn = rowm[ti * 4 + i];
#pragma unroll
            for (int j = 0; j < 4; j++)
                Ss[(ti * 4 + i) * SSTR + tj * 4 + j] = __expf(acc[i][j] - mn);
        }
        __syncthreads();

        // ---- stats 2: row sum, update l ----
        if (tid < AT_BM) {
            const float* srow = &Ss[tid * SSTR];
            float sum = 0.f;
#pragma unroll 8
            for (int j = 0; j < AT_BN; j++) sum += srow[j];
            rowl[tid] = rowl[tid] * rowa[tid] + sum;
        }
        __syncthreads();

        // ---- PV accumulate: thread owns (row ro, 32 cols cg*32..) ----
        const float a = rowa[ro];
#pragma unroll
        for (int u = 0; u < 32; u++) o[u] *= a;
        const float* prow = &Ss[ro * SSTR];
        for (int j = 0; j < AT_BN; j++) {
            const float p = prow[j];
            const float4* vr = (const float4*)&Vs[j * DV + cg * 32];
#pragma unroll
            for (int u = 0; u < 8; u++) {
                const float4 v4 = vr[u];
                o[u * 4 + 0] = fmaf(p, v4.x, o[u * 4 + 0]);
                o[u * 4 + 1] = fmaf(p, v4.y, o[u * 4 + 1]);
                o[u * 4 + 2] = fmaf(p, v4.z, o[u * 4 + 2]);
                o[u * 4 + 3] = fmaf(p, v4.w, o[u * 4 + 3]);
            }
        }
        __syncthreads();
    }

    // ---- write normalized output ----
    const float invl = 1.f / rowl[ro];
    const size_t obase = (size_t)(b * S_ + q0 + ro) * (NH * DV) + h * DV + cg * 32;
#pragma unroll
    for (int u = 0; u < 32; u++) g_att[obase + u] = o[u] * invl;
}

// ---------------- launch ----------------
extern "C" void kernel_launch(void* const* d_in, const int* in_sizes, int n_in,
                              void* d_out, int out_size)
{
    const float* x     = (const float*)d_in[0];
    const float* Wq    = (const float*)d_in[1];
    const float* Wkv_a = (const float*)d_in[2];
    const float* knw   = (const float*)d_in[3];
    const float* Wkv_b = (const float*)d_in[4];
    const float* Wo    = (const float*)d_in[5];
    float* out = (float*)d_out;

    static float *p_q, *p_kva, *p_ckv, *p_kvb, *p_att;
    static bool init = false;
    if (!init) {
        cudaGetSymbolAddress((void**)&p_q,   g_q);
        cudaGetSymbolAddress((void**)&p_kva, g_kva);
        cudaGetSymbolAddress((void**)&p_ckv, g_ckv);
        cudaGetSymbolAddress((void**)&p_kvb, g_kvb);
        cudaGetSymbolAddress((void**)&p_att, g_att);
        cudaFuncSetAttribute(attn_kernel,
                             cudaFuncAttributeMaxDynamicSharedMemorySize,
                             ATT_SMEM_BYTES);
        init = true;
    }

    const dim3 blk(256);
    // q = x @ Wq   [4096,2048]@[2048,3072]
    sgemm128<<<dim3(HQ / 128, BS / 128), blk>>>(x, Wq, p_q, BS, HQ, DM);
    // kva = x @ Wkv_a  [4096,2048]@[2048,576]
    sgemm128<<<dim3((KVA_N + 127) / 128, BS / 128), blk>>>(x, Wkv_a, p_kva, BS, KVA_N, DM);
    // rmsnorm + rope
    prep_kernel<<<BS, 256>>>(knw);
    // kvb = ckv @ Wkv_b  [4096,512]@[512,4096]
    sgemm128<<<dim3(HKV / 128, BS / 128), blk>>>(p_ckv, Wkv_b, p_kvb, BS, HKV, DKVL);
    // attention
    attn_kernel<<<dim3(S_ / AT_BM, NH, B_), 256, ATT_SMEM_BYTES>>>();
    // out = att @ Wo  [4096,2048]@[2048,2048]
    sgemm128<<<dim3(DM / 128, BS / 128), blk>>>(p_att, Wo, out, BS, DM, DM);
}

// round 2
// speedup vs baseline: 6.7921x; 6.7921x over previous
#include <cuda_runtime.h>
#include <math.h>

// ---------------- problem dims ----------------
#define B_      2
#define S_      2048
#define DM      2048
#define NH      16
#define DNOPE   128
#define DROPE   64
#define DQKD    192
#define DKVL    512
#define DV      128
#define BS      (B_*S_)          // 4096
#define HQ      (NH*DQKD)        // 3072
#define HKV     (NH*(DNOPE+DV))  // 4096
#define KVA_N   (DKVL+DROPE)     // 576
#define RMS_EPS 1.1920928955078125e-07f
#define ROPE_LC 0.28782313662425572f   // ln(10000)/32

// ---------------- scratch ----------------
__device__ float g_q  [BS*HQ];
__device__ float g_kva[BS*KVA_N];
__device__ float g_ckv[BS*DKVL];
__device__ float g_kr [BS*DROPE];
__device__ float g_kvb[BS*HKV];
__device__ float g_att[BS*(NH*DV)];

// ---------------- tf32 helpers ----------------
__device__ __forceinline__ unsigned f2tf(float f) {
    unsigned u;
    asm("cvt.rna.tf32.f32 %0, %1;" : "=r"(u) : "f"(f));
    return u;
}

__device__ __forceinline__ void mma8(float* c, unsigned a0, unsigned a1,
                                     unsigned a2, unsigned a3,
                                     unsigned b0, unsigned b1) {
    asm volatile(
        "mma.sync.aligned.m16n8k8.row.col.f32.tf32.tf32.f32 "
        "{%0,%1,%2,%3},{%4,%5,%6,%7},{%8,%9},{%0,%1,%2,%3};\n"
        : "+f"(c[0]), "+f"(c[1]), "+f"(c[2]), "+f"(c[3])
        : "r"(a0), "r"(a1), "r"(a2), "r"(a3), "r"(b0), "r"(b1));
}

// ---------------- tf32 tensor-core GEMM: C[M,N] = A[M,K] @ B[K,N] -----------
// 128x128x32 tile, 256 threads (8 warps, 4x2), per-warp 32x64.
// Requires: M%128==0, K%32==0. N guarded (and N%4==0).
__global__ void __launch_bounds__(256)
gemm_tf32(const float* __restrict__ A, const float* __restrict__ Bm,
          float* __restrict__ C, int M, int N, int K)
{
    __shared__ unsigned As[128 * 36];   // [m][k], stride 36 (≡4 mod 32)
    __shared__ unsigned Bs[32 * 136];   // [k][n], stride 136 (≡8 mod 32)

    const int tid  = threadIdx.x;
    const int wid  = tid >> 5;
    const int lane = tid & 31;
    const int lr   = lane >> 2;   // 0..7
    const int lc   = lane & 3;    // 0..3
    const int wm   = wid & 3;     // 0..3 -> 32-row strip
    const int wn   = wid >> 2;    // 0..1 -> 64-col strip
    const int m0   = blockIdx.y * 128;
    const int n0   = blockIdx.x * 128;

    float acc[2][8][4];
#pragma unroll
    for (int i = 0; i < 2; i++)
#pragma unroll
        for (int j = 0; j < 8; j++)
#pragma unroll
            for (int k = 0; k < 4; k++) acc[i][j][k] = 0.f;

    for (int k0 = 0; k0 < K; k0 += 32) {
        // A tile: 128 rows x 32 cols = 1024 float4
#pragma unroll
        for (int i = 0; i < 4; i++) {
            const int idx = tid + i * 256;
            const int m = idx >> 3, k4 = idx & 7;
            const float4 v = *(const float4*)(A + (size_t)(m0 + m) * K + k0 + k4 * 4);
            uint4 u = make_uint4(f2tf(v.x), f2tf(v.y), f2tf(v.z), f2tf(v.w));
            *(uint4*)&As[m * 36 + k4 * 4] = u;
        }
        // B tile: 32 rows x 128 cols = 1024 float4 (guarded on N)
#pragma unroll
        for (int i = 0; i < 4; i++) {
            const int idx = tid + i * 256;
            const int kk = idx >> 5, n4 = idx & 31;
            const int nc = n0 + n4 * 4;
            float4 v = make_float4(0.f, 0.f, 0.f, 0.f);
            if (nc < N) v = *(const float4*)(Bm + (size_t)(k0 + kk) * N + nc);
            uint4 u = make_uint4(f2tf(v.x), f2tf(v.y), f2tf(v.z), f2tf(v.w));
            *(uint4*)&Bs[kk * 136 + n4 * 4] = u;
        }
        __syncthreads();

#pragma unroll
        for (int ks = 0; ks < 4; ks++) {
            const int kb = ks * 8 + lc;
            unsigned a[2][4];
#pragma unroll
            for (int mt = 0; mt < 2; mt++) {
                const int mb = wm * 32 + mt * 16;
                a[mt][0] = As[(mb + lr) * 36 + kb];
                a[mt][1] = As[(mb + lr + 8) * 36 + kb];
                a[mt][2] = As[(mb + lr) * 36 + kb + 4];
                a[mt][3] = As[(mb + lr + 8) * 36 + kb + 4];
            }
#pragma unroll
            for (int nt = 0; nt < 8; nt++) {
                const int nb = wn * 64 + nt * 8 + lr;
                const unsigned b0 = Bs[kb * 136 + nb];
                const unsigned b1 = Bs[(kb + 4) * 136 + nb];
                mma8(acc[0][nt], a[0][0], a[0][1], a[0][2], a[0][3], b0, b1);
                mma8(acc[1][nt], a[1][0], a[1][1], a[1][2], a[1][3], b0, b1);
            }
        }
        __syncthreads();
    }

#pragma unroll
    for (int mt = 0; mt < 2; mt++)
#pragma unroll
        for (int nt = 0; nt < 8; nt++) {
            const int row = m0 + wm * 32 + mt * 16 + lr;
            const int col = n0 + wn * 64 + nt * 8 + 2 * lc;
            if (col < N) {
                *(float2*)(C + (size_t)row * N + col) =
                    make_float2(acc[mt][nt][0], acc[mt][nt][1]);
                *(float2*)(C + (size_t)(row + 8) * N + col) =
                    make_float2(acc[mt][nt][2], acc[mt][nt][3]);
            }
        }
}

// ---------------- prep: RMSNorm(c_kv), RoPE(k_rope), RoPE(q) -----------------
__global__ void prep_kernel(const float* __restrict__ w)
{
    const int row = blockIdx.x;
    const int s   = row % S_;
    const int tid = threadIdx.x;

    const float c0 = g_kva[(size_t)row * KVA_N + tid];
    const float c1 = g_kva[(size_t)row * KVA_N + tid + 256];
    float ss = c0 * c0 + c1 * c1;
#pragma unroll
    for (int o = 16; o > 0; o >>= 1) ss += __shfl_xor_sync(0xffffffffu, ss, o);
    __shared__ float red[8];
    if ((tid & 31) == 0) red[tid >> 5] = ss;
    __syncthreads();
    if (tid == 0) {
        float v = 0.f;
#pragma unroll
        for (int i = 0; i < 8; i++) v += red[i];
        red[0] = v;
    }
    __syncthreads();
    const float inv = rsqrtf(red[0] * (1.f / 512.f) + RMS_EPS);
    g_ckv[(size_t)row * DKVL + tid]       = c0 * inv * w[tid];
    g_ckv[(size_t)row * DKVL + tid + 256] = c1 * inv * w[tid + 256];

    if (tid < 32) {
        const float fr = expf(-(float)tid * ROPE_LC);
        const float t  = (float)s * fr;
        const float cs = cosf(t), sn = sinf(t);
        const float x1 = g_kva[(size_t)row * KVA_N + DKVL + 2 * tid];
        const float x2 = g_kva[(size_t)row * KVA_N + DKVL + 2 * tid + 1];
        g_kr[(size_t)row * DROPE + 2 * tid]     = x1 * cs - x2 * sn;
        g_kr[(size_t)row * DROPE + 2 * tid + 1] = x2 * cs + x1 * sn;
    }

    for (int p = tid; p < NH * 32; p += 256) {
        const int h = p >> 5, i = p & 31;
        const float fr = expf(-(float)i * ROPE_LC);
        const float t  = (float)s * fr;
        const float cs = cosf(t), sn = sinf(t);
        const size_t base = (size_t)row * HQ + h * DQKD + DNOPE + 2 * i;
        const float x1 = g_q[base], x2 = g_q[base + 1];
        g_q[base]     = x1 * cs - x2 * sn;
        g_q[base + 1] = x2 * cs + x1 * sn;
    }
}

// ---------------- tensor-core flash attention ----------------
// grid (S/64, NH, B), 128 threads (4 warps). BM=BN=64, tf32 mma.
#define QS_STR 196   // [row m][d]  (196 % 32 == 4)
#define KS_STR 196   // [key j][d]
#define VS_STR 136   // [key j][d]  (136 % 32 == 8)
#define PS_STR 68    // [row m][j]  (68 % 32 == 4)

#define QS_OFF 0
#define KS_OFF (QS_OFF + 64 * QS_STR)
#define VS_OFF (KS_OFF + 64 * KS_STR)
#define PS_OFF (VS_OFF + 64 * VS_STR)
#define ATT_WORDS (PS_OFF + 64 * PS_STR)
#define ATT_BYTES (ATT_WORDS * 4)

__global__ void __launch_bounds__(128)
attn_tc()
{
    extern __shared__ unsigned sm[];
    unsigned* Qs = sm + QS_OFF;
    unsigned* Ks = sm + KS_OFF;
    unsigned* Vs = sm + VS_OFF;
    unsigned* Ps = sm + PS_OFF;

    const int qblk = blockIdx.x;
    const int h    = blockIdx.y;
    const int b    = blockIdx.z;
    const int tid  = threadIdx.x;
    const int w    = tid >> 5;
    const int lane = tid & 31;
    const int lr   = lane >> 2;
    const int lc   = lane & 3;
    const int w16  = w * 16;
    const int q0   = qblk * 64;
    const int bS   = b * S_;

    const float scale = 0.07216878364870323f; // 1/sqrt(192)

    // ---- load Q tile (64 x 192), convert to tf32 ----
#pragma unroll
    for (int i = 0; i < 24; i++) {
        const int idx = tid + i * 128;      // 3072 float4
        const int r = idx / 48, d4 = idx % 48;
        const float4 v = *(const float4*)(g_q + (size_t)(bS + q0 + r) * HQ + h * DQKD + d4 * 4);
        *(uint4*)&Qs[r * QS_STR + d4 * 4] =
            make_uint4(f2tf(v.x), f2tf(v.y), f2tf(v.z), f2tf(v.w));
    }

    float oacc[16][4];
#pragma unroll
    for (int i = 0; i < 16; i++)
#pragma unroll
        for (int j = 0; j < 4; j++) oacc[i][j] = 0.f;
    float m0v = -1e30f, m1v = -1e30f, l0 = 0.f, l1 = 0.f;

    const int row0g = q0 + w16 + lr;
    const int row1g = row0g + 8;

    __syncthreads();

    for (int kt = 0; kt <= qblk; kt++) {
        const int k0 = kt * 64;

        // K nope part: [j][0..127]
#pragma unroll
        for (int i = 0; i < 16; i++) {
            const int idx = tid + i * 128;  // 2048 f4
            const int j = idx >> 5, d4 = idx & 31;
            const float4 v = *(const float4*)(g_kvb + (size_t)(bS + k0 + j) * HKV + h * 256 + d4 * 4);
            *(uint4*)&Ks[j * KS_STR + d4 * 4] =
                make_uint4(f2tf(v.x), f2tf(v.y), f2tf(v.z), f2tf(v.w));
        }
        // K rope part: [j][128..191]
#pragma unroll
        for (int i = 0; i < 8; i++) {
            const int idx = tid + i * 128;  // 1024 f4
            const int j = idx >> 4, d4 = idx & 15;
            const float4 v = *(const float4*)(g_kr + (size_t)(bS + k0 + j) * DROPE + d4 * 4);
            *(uint4*)&Ks[j * KS_STR + 128 + d4 * 4] =
                make_uint4(f2tf(v.x), f2tf(v.y), f2tf(v.z), f2tf(v.w));
        }
        // V: [j][0..127]
#pragma unroll
        for (int i = 0; i < 16; i++) {
            const int idx = tid + i * 128;
            const int j = idx >> 5, d4 = idx & 31;
            const float4 v = *(const float4*)(g_kvb + (size_t)(bS + k0 + j) * HKV + h * 256 + 128 + d4 * 4);
            *(uint4*)&Vs[j * VS_STR + d4 * 4] =
                make_uint4(f2tf(v.x), f2tf(v.y), f2tf(v.z), f2tf(v.w));
        }
        __syncthreads();

        // ---- S = Q @ K^T : per warp 16x64, 24 k-steps ----
        float sacc[8][4];
#pragma unroll
        for (int i = 0; i < 8; i++)
#pragma unroll
            for (int j = 0; j < 4; j++) sacc[i][j] = 0.f;

#pragma unroll
        for (int ks = 0; ks < 24; ks++) {
            const int kb = ks * 8 + lc;
            const unsigned a0 = Qs[(w16 + lr) * QS_STR + kb];
            const unsigned a1 = Qs[(w16 + lr + 8) * QS_STR + kb];
            const unsigned a2 = Qs[(w16 + lr) * QS_STR + kb + 4];
            const unsigned a3 = Qs[(w16 + lr + 8) * QS_STR + kb + 4];
#pragma unroll
            for (int nt = 0; nt < 8; nt++) {
                const unsigned b0 = Ks[(nt * 8 + lr) * KS_STR + kb];
                const unsigned b1 = Ks[(nt * 8 + lr) * KS_STR + kb + 4];
                mma8(sacc[nt], a0, a1, a2, a3, b0, b1);
            }
        }

        // ---- mask + scale, row max ----
        const bool diag = (kt == qblk);
        float mt0 = -1e30f, mt1 = -1e30f;
#pragma unroll
        for (int nt = 0; nt < 8; nt++) {
            const int jb = k0 + nt * 8 + 2 * lc;
#pragma unroll
            for (int c = 0; c < 4; c++) {
                float s = sacc[nt][c] * scale;
                const int jg = jb + (c & 1);
                const int rg = (c < 2) ? row0g : row1g;
                if (diag && jg > rg) s = -1e30f;
                sacc[nt][c] = s;
                if (c < 2) mt0 = fmaxf(mt0, s); else mt1 = fmaxf(mt1, s);
            }
        }
        mt0 = fmaxf(mt0, __shfl_xor_sync(0xffffffffu, mt0, 1));
        mt0 = fmaxf(mt0, __shfl_xor_sync(0xffffffffu, mt0, 2));
        mt1 = fmaxf(mt1, __shfl_xor_sync(0xffffffffu, mt1, 1));
        mt1 = fmaxf(mt1, __shfl_xor_sync(0xffffffffu, mt1, 2));

        const float mn0 = fmaxf(m0v, mt0);
        const float mn1 = fmaxf(m1v, mt1);
        const float al0 = __expf(m0v - mn0);
        const float al1 = __expf(m1v - mn1);
        m0v = mn0; m1v = mn1;

        // ---- P = exp(S - m), store tf32 to Ps, accumulate row sums ----
        float rs0 = 0.f, rs1 = 0.f;
#pragma unroll
        for (int nt = 0; nt < 8; nt++) {
            const int jj = nt * 8 + 2 * lc;
            const float p0 = __expf(sacc[nt][0] - mn0);
            const float p1 = __expf(sacc[nt][1] - mn0);
            const float p2 = __expf(sacc[nt][2] - mn1);
            const float p3 = __expf(sacc[nt][3] - mn1);
            rs0 += p0 + p1; rs1 += p2 + p3;
            Ps[(w16 + lr) * PS_STR + jj]     = f2tf(p0);
            Ps[(w16 + lr) * PS_STR + jj + 1] = f2tf(p1);
            Ps[(w16 + lr + 8) * PS_STR + jj]     = f2tf(p2);
            Ps[(w16 + lr + 8) * PS_STR + jj + 1] = f2tf(p3);
        }
        rs0 += __shfl_xor_sync(0xffffffffu, rs0, 1);
        rs0 += __shfl_xor_sync(0xffffffffu, rs0, 2);
        rs1 += __shfl_xor_sync(0xffffffffu, rs1, 1);
        rs1 += __shfl_xor_sync(0xffffffffu, rs1, 2);
        l0 = l0 * al0 + rs0;
        l1 = l1 * al1 + rs1;

        // ---- rescale O ----
#pragma unroll
        for (int nt = 0; nt < 16; nt++) {
            oacc[nt][0] *= al0; oacc[nt][1] *= al0;
            oacc[nt][2] *= al1; oacc[nt][3] *= al1;
        }
        __syncwarp();

        // ---- O += P @ V : 8 k-steps, 16 n-tiles ----
#pragma unroll
        for (int ks = 0; ks < 8; ks++) {
            const int kb = ks * 8 + lc;
            const unsigned a0 = Ps[(w16 + lr) * PS_STR + kb];
            const unsigned a1 = Ps[(w16 + lr + 8) * PS_STR + kb];
            const unsigned a2 = Ps[(w16 + lr) * PS_STR + kb + 4];
            const unsigned a3 = Ps[(w16 + lr + 8) * PS_STR + kb + 4];
#pragma unroll
            for (int nt = 0; nt < 16; nt++) {
                const unsigned b0 = Vs[kb * VS_STR + nt * 8 + lr];
                const unsigned b1 = Vs[(kb + 4) * VS_STR + nt * 8 + lr];
                mma8(oacc[nt], a0, a1, a2, a3, b0, b1);
            }
        }
        __syncthreads();
    }

    // ---- normalize + write ----
    const float inv0 = 1.f / l0;
    const float inv1 = 1.f / l1;
#pragma unroll
    for (int nt = 0; nt < 16; nt++) {
        const int col = h * DV + nt * 8 + 2 * lc;
        *(float2*)(g_att + (size_t)(bS + row0g) * (NH * DV) + col) =
            make_float2(oacc[nt][0] * inv0, oacc[nt][1] * inv0);
        *(float2*)(g_att + (size_t)(bS + row1g) * (NH * DV) + col) =
            make_float2(oacc[nt][2] * inv1, oacc[nt][3] * inv1);
    }
}

// ---------------- launch ----------------
extern "C" void kernel_launch(void* const* d_in, const int* in_sizes, int n_in,
                              void* d_out, int out_size)
{
    const float* x     = (const float*)d_in[0];
    const float* Wq    = (const float*)d_in[1];
    const float* Wkv_a = (const float*)d_in[2];
    const float* knw   = (const float*)d_in[3];
    const float* Wkv_b = (const float*)d_in[4];
    const float* Wo    = (const float*)d_in[5];
    float* out = (float*)d_out;

    static float *p_q, *p_kva, *p_ckv, *p_kvb, *p_att;
    static bool init = false;
    if (!init) {
        cudaGetSymbolAddress((void**)&p_q,   g_q);
        cudaGetSymbolAddress((void**)&p_kva, g_kva);
        cudaGetSymbolAddress((void**)&p_ckv, g_ckv);
        cudaGetSymbolAddress((void**)&p_kvb, g_kvb);
        cudaGetSymbolAddress((void**)&p_att, g_att);
        cudaFuncSetAttribute(attn_tc,
                             cudaFuncAttributeMaxDynamicSharedMemorySize,
                             ATT_BYTES);
        init = true;
    }

    const dim3 blk(256);
    gemm_tf32<<<dim3(HQ / 128, BS / 128), blk>>>(x, Wq, p_q, BS, HQ, DM);
    gemm_tf32<<<dim3((KVA_N + 127) / 128, BS / 128), blk>>>(x, Wkv_a, p_kva, BS, KVA_N, DM);
    prep_kernel<<<BS, 256>>>(knw);
    gemm_tf32<<<dim3(HKV / 128, BS / 128), blk>>>(p_ckv, Wkv_b, p_kvb, BS, HKV, DKVL);
    attn_tc<<<dim3(S_ / 64, NH, B_), 128, ATT_BYTES>>>();
    gemm_tf32<<<dim3(DM / 128, BS / 128), blk>>>(p_att, Wo, out, BS, DM, DM);
}

// round 3
// speedup vs baseline: 6.9844x; 1.0283x over previous
#include <cuda_runtime.h>
#include <math.h>
#include <stdint.h>

// ---------------- problem dims ----------------
#define B_      2
#define S_      2048
#define DM      2048
#define NH      16
#define DNOPE   128
#define DROPE   64
#define DQKD    192
#define DKVL    512
#define DV      128
#define BS      (B_*S_)          // 4096
#define HQ      (NH*DQKD)        // 3072
#define HKV     (NH*(DNOPE+DV))  // 4096
#define KVA_N   (DKVL+DROPE)     // 576
#define RMS_EPS 1.1920928955078125e-07f
#define ROPE_LC 0.28782313662425572f   // ln(10000)/32

// ---------------- scratch ----------------
__device__ float g_q  [BS*HQ];
__device__ float g_kva[BS*KVA_N];
__device__ float g_ckv[BS*DKVL];
__device__ float g_kr [BS*DROPE];
__device__ float g_kvb[BS*HKV];
__device__ float g_att[BS*(NH*DV)];

// ---------------- helpers ----------------
__device__ __forceinline__ unsigned f2tf(float f) {
    unsigned u;
    asm("cvt.rna.tf32.f32 %0, %1;" : "=r"(u) : "f"(f));
    return u;
}

__device__ __forceinline__ void mma8(float* c, unsigned a0, unsigned a1,
                                     unsigned a2, unsigned a3,
                                     unsigned b0, unsigned b1) {
    asm volatile(
        "mma.sync.aligned.m16n8k8.row.col.f32.tf32.tf32.f32 "
        "{%0,%1,%2,%3},{%4,%5,%6,%7},{%8,%9},{%0,%1,%2,%3};\n"
        : "+f"(c[0]), "+f"(c[1]), "+f"(c[2]), "+f"(c[3])
        : "r"(a0), "r"(a1), "r"(a2), "r"(a3), "r"(b0), "r"(b1));
}

__device__ __forceinline__ void cp_async16(uint32_t dst, const float* src, int srcBytes) {
    asm volatile("cp.async.cg.shared.global [%0], [%1], 16, %2;\n"
                 :: "r"(dst), "l"(src), "r"(srcBytes));
}
#define CP_COMMIT() asm volatile("cp.async.commit_group;\n" ::: "memory")
#define CP_WAIT(n)  asm volatile("cp.async.wait_group %0;\n" :: "n"(n) : "memory")

// ---------------- tf32 GEMM with cp.async double buffering ------------------
// C[M,N] = A[M,K] @ B[K,N]. 128x128x32 tile, 256 thr (8 warps), warp 32x64.
// M%128==0, K%32==0, N guarded (N%4==0).
#define GA_WORDS 4608   // 128*36
#define GB_WORDS 4352   // 32*136
#define GEMM_SMEM_BYTES ((2*GA_WORDS + 2*GB_WORDS) * 4)

__global__ void __launch_bounds__(256)
gemm_tf32(const float* __restrict__ A, const float* __restrict__ Bm,
          float* __restrict__ C, int M, int N, int K)
{
    extern __shared__ float gsm[];
    float* Asf = gsm;                   // [2][128][36]
    float* Bsf = gsm + 2 * GA_WORDS;    // [2][32][136]
    const uint32_t sA = (uint32_t)__cvta_generic_to_shared(Asf);
    const uint32_t sB = (uint32_t)__cvta_generic_to_shared(Bsf);

    const int tid  = threadIdx.x;
    const int wid  = tid >> 5;
    const int lane = tid & 31;
    const int lr   = lane >> 2;
    const int lc   = lane & 3;
    const int wm   = wid & 3;
    const int wn   = wid >> 2;
    const int m0   = blockIdx.y * 128;
    const int n0   = blockIdx.x * 128;

    float acc[2][8][4];
#pragma unroll
    for (int i = 0; i < 2; i++)
#pragma unroll
        for (int j = 0; j < 8; j++)
#pragma unroll
            for (int k = 0; k < 4; k++) acc[i][j][k] = 0.f;

    auto loadTile = [&](int stage, int k0) {
        const uint32_t aB = sA + stage * GA_WORDS * 4;
        const uint32_t bB = sB + stage * GB_WORDS * 4;
#pragma unroll
        for (int i = 0; i < 4; i++) {
            const int idx = tid + i * 256;
            const int m = idx >> 3, k4 = idx & 7;
            cp_async16(aB + (m * 36 + k4 * 4) * 4,
                       A + (size_t)(m0 + m) * K + k0 + k4 * 4, 16);
        }
#pragma unroll
        for (int i = 0; i < 4; i++) {
            const int idx = tid + i * 256;
            const int kk = idx >> 5, n4 = idx & 31;
            const int nc = n0 + n4 * 4;
            const float* src = Bm + (size_t)(k0 + kk) * N + (nc < N ? nc : N - 4);
            cp_async16(bB + (kk * 136 + n4 * 4) * 4, src, nc < N ? 16 : 0);
        }
    };

    const int T = K >> 5;
    loadTile(0, 0);
    CP_COMMIT();

    for (int it = 0; it < T; it++) {
        const int buf = it & 1;
        if (it + 1 < T) { loadTile(buf ^ 1, (it + 1) * 32); CP_COMMIT(); CP_WAIT(1); }
        else            { CP_WAIT(0); }
        __syncthreads();

        const float* Af = Asf + buf * GA_WORDS;
        const float* Bf = Bsf + buf * GB_WORDS;
#pragma unroll
        for (int ks = 0; ks < 4; ks++) {
            const int kb = ks * 8 + lc;
            unsigned a[2][4];
#pragma unroll
            for (int mt = 0; mt < 2; mt++) {
                const int mb = wm * 32 + mt * 16;
                a[mt][0] = f2tf(Af[(mb + lr) * 36 + kb]);
                a[mt][1] = f2tf(Af[(mb + lr + 8) * 36 + kb]);
                a[mt][2] = f2tf(Af[(mb + lr) * 36 + kb + 4]);
                a[mt][3] = f2tf(Af[(mb + lr + 8) * 36 + kb + 4]);
            }
#pragma unroll
            for (int nt = 0; nt < 8; nt++) {
                const int nb = wn * 64 + nt * 8 + lr;
                const unsigned b0 = f2tf(Bf[kb * 136 + nb]);
                const unsigned b1 = f2tf(Bf[(kb + 4) * 136 + nb]);
                mma8(acc[0][nt], a[0][0], a[0][1], a[0][2], a[0][3], b0, b1);
                mma8(acc[1][nt], a[1][0], a[1][1], a[1][2], a[1][3], b0, b1);
            }
        }
        __syncthreads();
    }

#pragma unroll
    for (int mt = 0; mt < 2; mt++)
#pragma unroll
        for (int nt = 0; nt < 8; nt++) {
            const int row = m0 + wm * 32 + mt * 16 + lr;
            const int col = n0 + wn * 64 + nt * 8 + 2 * lc;
            if (col < N) {
                *(float2*)(C + (size_t)row * N + col) =
                    make_float2(acc[mt][nt][0], acc[mt][nt][1]);
                *(float2*)(C + (size_t)(row + 8) * N + col) =
                    make_float2(acc[mt][nt][2], acc[mt][nt][3]);
            }
        }
}

// ---------------- prep: RMSNorm(c_kv), RoPE(k_rope), RoPE(q) -----------------
__global__ void prep_kernel(const float* __restrict__ w)
{
    const int row = blockIdx.x;
    const int s   = row % S_;
    const int tid = threadIdx.x;

    const float c0 = g_kva[(size_t)row * KVA_N + tid];
    const float c1 = g_kva[(size_t)row * KVA_N + tid + 256];
    float ss = c0 * c0 + c1 * c1;
#pragma unroll
    for (int o = 16; o > 0; o >>= 1) ss += __shfl_xor_sync(0xffffffffu, ss, o);
    __shared__ float red[8];
    if ((tid & 31) == 0) red[tid >> 5] = ss;
    __syncthreads();
    if (tid == 0) {
        float v = 0.f;
#pragma unroll
        for (int i = 0; i < 8; i++) v += red[i];
        red[0] = v;
    }
    __syncthreads();
    const float inv = rsqrtf(red[0] * (1.f / 512.f) + RMS_EPS);
    g_ckv[(size_t)row * DKVL + tid]       = c0 * inv * w[tid];
    g_ckv[(size_t)row * DKVL + tid + 256] = c1 * inv * w[tid + 256];

    if (tid < 32) {
        const float fr = expf(-(float)tid * ROPE_LC);
        const float t  = (float)s * fr;
        const float cs = cosf(t), sn = sinf(t);
        const float x1 = g_kva[(size_t)row * KVA_N + DKVL + 2 * tid];
        const float x2 = g_kva[(size_t)row * KVA_N + DKVL + 2 * tid + 1];
        g_kr[(size_t)row * DROPE + 2 * tid]     = x1 * cs - x2 * sn;
        g_kr[(size_t)row * DROPE + 2 * tid + 1] = x2 * cs + x1 * sn;
    }

    for (int p = tid; p < NH * 32; p += 256) {
        const int h = p >> 5, i = p & 31;
        const float fr = expf(-(float)i * ROPE_LC);
        const float t  = (float)s * fr;
        const float cs = cosf(t), sn = sinf(t);
        const size_t base = (size_t)row * HQ + h * DQKD + DNOPE + 2 * i;
        const float x1 = g_q[base], x2 = g_q[base + 1];
        g_q[base]     = x1 * cs - x2 * sn;
        g_q[base + 1] = x2 * cs + x1 * sn;
    }
}

// ---------------- tensor-core flash attention (BM=128, BN=64) ----------------
// grid (S/128, NH, B), 256 threads (8 warps x 16 rows).
#define QS_STR 196
#define KS_STR 196
#define VS_STR 136
#define PS_STR 68

#define QS_OFF 0
#define KS_OFF (QS_OFF + 128 * QS_STR)
#define VS_OFF (KS_OFF + 64 * KS_STR)
#define PS_OFF (VS_OFF + 64 * VS_STR)
#define ATT_WORDS (PS_OFF + 128 * PS_STR)
#define ATT_BYTES (ATT_WORDS * 4)

__global__ void __launch_bounds__(256)
attn_tc()
{
    extern __shared__ unsigned sm[];
    unsigned* Qs = sm + QS_OFF;
    unsigned* Ks = sm + KS_OFF;
    unsigned* Vs = sm + VS_OFF;
    unsigned* Ps = sm + PS_OFF;

    const int qblk = blockIdx.x;
    const int h    = blockIdx.y;
    const int b    = blockIdx.z;
    const int tid  = threadIdx.x;
    const int w    = tid >> 5;
    const int lane = tid & 31;
    const int lr   = lane >> 2;
    const int lc   = lane & 3;
    const int w16  = w * 16;
    const int q0   = qblk * 128;
    const int bS   = b * S_;

    const float scale = 0.07216878364870323f; // 1/sqrt(192)

    // ---- load Q tile (128 x 192), convert to tf32 ----
#pragma unroll
    for (int i = 0; i < 24; i++) {
        const int idx = tid + i * 256;        // 6144 float4
        const int r = idx / 48, d4 = idx % 48;
        const float4 v = *(const float4*)(g_q + (size_t)(bS + q0 + r) * HQ + h * DQKD + d4 * 4);
        *(uint4*)&Qs[r * QS_STR + d4 * 4] =
            make_uint4(f2tf(v.x), f2tf(v.y), f2tf(v.z), f2tf(v.w));
    }

    float oacc[16][4];
#pragma unroll
    for (int i = 0; i < 16; i++)
#pragma unroll
        for (int j = 0; j < 4; j++) oacc[i][j] = 0.f;
    float m0v = -1e30f, m1v = -1e30f, l0 = 0.f, l1 = 0.f;

    const int row0g = q0 + w16 + lr;
    const int row1g = row0g + 8;
    const int lastNeeded = q0 + w16 + 15;  // max row this warp owns

    __syncthreads();

    const int ktMax = 2 * qblk + 1;
    for (int kt = 0; kt <= ktMax; kt++) {
        const int k0 = kt * 64;

        // K nope
#pragma unroll
        for (int i = 0; i < 8; i++) {
            const int idx = tid + i * 256;    // 2048 f4
            const int j = idx >> 5, d4 = idx & 31;
            const float4 v = *(const float4*)(g_kvb + (size_t)(bS + k0 + j) * HKV + h * 256 + d4 * 4);
            *(uint4*)&Ks[j * KS_STR + d4 * 4] =
                make_uint4(f2tf(v.x), f2tf(v.y), f2tf(v.z), f2tf(v.w));
        }
        // K rope
#pragma unroll
        for (int i = 0; i < 4; i++) {
            const int idx = tid + i * 256;    // 1024 f4
            const int j = idx >> 4, d4 = idx & 15;
            const float4 v = *(const float4*)(g_kr + (size_t)(bS + k0 + j) * DROPE + d4 * 4);
            *(uint4*)&Ks[j * KS_STR + 128 + d4 * 4] =
                make_uint4(f2tf(v.x), f2tf(v.y), f2tf(v.z), f2tf(v.w));
        }
        // V
#pragma unroll
        for (int i = 0; i < 8; i++) {
            const int idx = tid + i * 256;
            const int j = idx >> 5, d4 = idx & 31;
            const float4 v = *(const float4*)(g_kvb + (size_t)(bS + k0 + j) * HKV + h * 256 + 128 + d4 * 4);
            *(uint4*)&Vs[j * VS_STR + d4 * 4] =
                make_uint4(f2tf(v.x), f2tf(v.y), f2tf(v.z), f2tf(v.w));
        }
        __syncthreads();

        if (k0 <= lastNeeded) {
            // ---- S = Q @ K^T : per warp 16x64, 24 k-steps ----
            float sacc[8][4];
#pragma unroll
            for (int i = 0; i < 8; i++)
#pragma unroll
                for (int j = 0; j < 4; j++) sacc[i][j] = 0.f;

#pragma unroll
            for (int ks = 0; ks < 24; ks++) {
                const int kb = ks * 8 + lc;
                const unsigned a0 = Qs[(w16 + lr) * QS_STR + kb];
                const unsigned a1 = Qs[(w16 + lr + 8) * QS_STR + kb];
                const unsigned a2 = Qs[(w16 + lr) * QS_STR + kb + 4];
                const unsigned a3 = Qs[(w16 + lr + 8) * QS_STR + kb + 4];
#pragma unroll
                for (int nt = 0; nt < 8; nt++) {
                    const unsigned b0 = Ks[(nt * 8 + lr) * KS_STR + kb];
                    const unsigned b1 = Ks[(nt * 8 + lr) * KS_STR + kb + 4];
                    mma8(sacc[nt], a0, a1, a2, a3, b0, b1);
                }
            }

            // ---- mask + scale, row max ----
            const bool domask = (k0 + 63 > q0 + w16);
            float mt0 = -1e30f, mt1 = -1e30f;
#pragma unroll
            for (int nt = 0; nt < 8; nt++) {
                const int jb = k0 + nt * 8 + 2 * lc;
#pragma unroll
                for (int c = 0; c < 4; c++) {
                    float s = sacc[nt][c] * scale;
                    const int jg = jb + (c & 1);
                    const int rg = (c < 2) ? row0g : row1g;
                    if (domask && jg > rg) s = -1e30f;
                    sacc[nt][c] = s;
                    if (c < 2) mt0 = fmaxf(mt0, s); else mt1 = fmaxf(mt1, s);
                }
            }
            mt0 = fmaxf(mt0, __shfl_xor_sync(0xffffffffu, mt0, 1));
            mt0 = fmaxf(mt0, __shfl_xor_sync(0xffffffffu, mt0, 2));
            mt1 = fmaxf(mt1, __shfl_xor_sync(0xffffffffu, mt1, 1));
            mt1 = fmaxf(mt1, __shfl_xor_sync(0xffffffffu, mt1, 2));

            const float mn0 = fmaxf(m0v, mt0);
            const float mn1 = fmaxf(m1v, mt1);
            const float al0 = __expf(m0v - mn0);
            const float al1 = __expf(m1v - mn1);
            m0v = mn0; m1v = mn1;

            // ---- P = exp(S - m), store tf32, row sums ----
            float rs0 = 0.f, rs1 = 0.f;
#pragma unroll
            for (int nt = 0; nt < 8; nt++) {
                const int jj = nt * 8 + 2 * lc;
                const float p0 = __expf(sacc[nt][0] - mn0);
                const float p1 = __expf(sacc[nt][1] - mn0);
                const float p2 = __expf(sacc[nt][2] - mn1);
                const float p3 = __expf(sacc[nt][3] - mn1);
                rs0 += p0 + p1; rs1 += p2 + p3;
                Ps[(w16 + lr) * PS_STR + jj]         = f2tf(p0);
                Ps[(w16 + lr) * PS_STR + jj + 1]     = f2tf(p1);
                Ps[(w16 + lr + 8) * PS_STR + jj]     = f2tf(p2);
                Ps[(w16 + lr + 8) * PS_STR + jj + 1] = f2tf(p3);
            }
            rs0 += __shfl_xor_sync(0xffffffffu, rs0, 1);
            rs0 += __shfl_xor_sync(0xffffffffu, rs0, 2);
            rs1 += __shfl_xor_sync(0xffffffffu, rs1, 1);
            rs1 += __shfl_xor_sync(0xffffffffu, rs1, 2);
            l0 = l0 * al0 + rs0;
            l1 = l1 * al1 + rs1;

            // ---- rescale O ----
#pragma unroll
            for (int nt = 0; nt < 16; nt++) {
                oacc[nt][0] *= al0; oacc[nt][1] *= al0;
                oacc[nt][2] *= al1; oacc[nt][3] *= al1;
            }
            __syncwarp();

            // ---- O += P @ V ----
#pragma unroll
            for (int ks = 0; ks < 8; ks++) {
                const int kb = ks * 8 + lc;
                const unsigned a0 = Ps[(w16 + lr) * PS_STR + kb];
                const unsigned a1 = Ps[(w16 + lr + 8) * PS_STR + kb];
                const unsigned a2 = Ps[(w16 + lr) * PS_STR + kb + 4];
                const unsigned a3 = Ps[(w16 + lr + 8) * PS_STR + kb + 4];
#pragma unroll
                for (int nt = 0; nt < 16; nt++) {
                    const unsigned b0 = Vs[kb * VS_STR + nt * 8 + lr];
                    const unsigned b1 = Vs[(kb + 4) * VS_STR + nt * 8 + lr];
                    mma8(oacc[nt], a0, a1, a2, a3, b0, b1);
                }
            }
        }
        __syncthreads();
    }

    // ---- normalize + write ----
    const float inv0 = 1.f / l0;
    const float inv1 = 1.f / l1;
#pragma unroll
    for (int nt = 0; nt < 16; nt++) {
        const int col = h * DV + nt * 8 + 2 * lc;
        *(float2*)(g_att + (size_t)(bS + row0g) * (NH * DV) + col) =
            make_float2(oacc[nt][0] * inv0, oacc[nt][1] * inv0);
        *(float2*)(g_att + (size_t)(bS + row1g) * (NH * DV) + col) =
            make_float2(oacc[nt][2] * inv1, oacc[nt][3] * inv1);
    }
}

// ---------------- launch ----------------
extern "C" void kernel_launch(void* const* d_in, const int* in_sizes, int n_in,
                              void* d_out, int out_size)
{
    const float* x     = (const float*)d_in[0];
    const float* Wq    = (const float*)d_in[1];
    const float* Wkv_a = (const float*)d_in[2];
    const float* knw   = (const float*)d_in[3];
    const float* Wkv_b = (const float*)d_in[4];
    const float* Wo    = (const float*)d_in[5];
    float* out = (float*)d_out;

    static float *p_q, *p_kva, *p_ckv, *p_kvb, *p_att;
    static bool init = false;
    if (!init) {
        cudaGetSymbolAddress((void**)&p_q,   g_q);
        cudaGetSymbolAddress((void**)&p_kva, g_kva);
        cudaGetSymbolAddress((void**)&p_ckv, g_ckv);
        cudaGetSymbolAddress((void**)&p_kvb, g_kvb);
        cudaGetSymbolAddress((void**)&p_att, g_att);
        cudaFuncSetAttribute(attn_tc,
                             cudaFuncAttributeMaxDynamicSharedMemorySize,
                             ATT_BYTES);
        cudaFuncSetAttribute(gemm_tf32,
                             cudaFuncAttributeMaxDynamicSharedMemorySize,
                             GEMM_SMEM_BYTES);
        init = true;
    }

    const dim3 blk(256);
    gemm_tf32<<<dim3(HQ / 128, BS / 128), blk, GEMM_SMEM_BYTES>>>(x, Wq, p_q, BS, HQ, DM);
    gemm_tf32<<<dim3((KVA_N + 127) / 128, BS / 128), blk, GEMM_SMEM_BYTES>>>(x, Wkv_a, p_kva, BS, KVA_N, DM);
    prep_kernel<<<BS, 256>>>(knw);
    gemm_tf32<<<dim3(HKV / 128, BS / 128), blk, GEMM_SMEM_BYTES>>>(p_ckv, Wkv_b, p_kvb, BS, HKV, DKVL);
    attn_tc<<<dim3(S_ / 128, NH, B_), 256, ATT_BYTES>>>();
    gemm_tf32<<<dim3(DM / 128, BS / 128), blk, GEMM_SMEM_BYTES>>>(p_att, Wo, out, BS, DM, DM);
}

// round 5
// speedup vs baseline: 7.3654x; 1.0546x over previous
#include <cuda_runtime.h>
#include <math.h>
#include <stdint.h>

// ---------------- problem dims ----------------
#define B_      2
#define S_      2048
#define DM      2048
#define NH      16
#define DNOPE   128
#define DROPE   64
#define DQKD    192
#define DKVL    512
#define DV      128
#define BS      (B_*S_)          // 4096
#define HQ      (NH*DQKD)        // 3072
#define HKV     (NH*(DNOPE+DV))  // 4096
#define KVA_N   (DKVL+DROPE)     // 576
#define RMS_EPS 1.1920928955078125e-07f
#define ROPE_LC 0.28782313662425572f   // ln(10000)/32

// ---------------- scratch ----------------
__device__ float g_q  [BS*HQ];
__device__ float g_kva[BS*KVA_N];
__device__ float g_ckv[BS*DKVL];
__device__ float g_kr [BS*DROPE];
__device__ float g_kvb[BS*HKV];
__device__ float g_att[BS*(NH*DV)];
// pre-rounded (tf32) copies of inputs
__device__ float g_xr  [BS*DM];
__device__ float g_wq  [DM*HQ];
__device__ float g_wkva[DM*KVA_N];
__device__ float g_wkvb[DKVL*HKV];
__device__ float g_wo  [NH*DV*DM];

// ---------------- helpers ----------------
__device__ __forceinline__ unsigned f2tf(float f) {
    unsigned u;
    asm("cvt.rna.tf32.f32 %0, %1;" : "=r"(u) : "f"(f));
    return u;
}
__device__ __forceinline__ float tfr(float f) { return __uint_as_float(f2tf(f)); }

__device__ __forceinline__ void mma8(float* c, unsigned a0, unsigned a1,
                                     unsigned a2, unsigned a3,
                                     unsigned b0, unsigned b1) {
    asm volatile(
        "mma.sync.aligned.m16n8k8.row.col.f32.tf32.tf32.f32 "
        "{%0,%1,%2,%3},{%4,%5,%6,%7},{%8,%9},{%0,%1,%2,%3};\n"
        : "+f"(c[0]), "+f"(c[1]), "+f"(c[2]), "+f"(c[3])
        : "r"(a0), "r"(a1), "r"(a2), "r"(a3), "r"(b0), "r"(b1));
}

__device__ __forceinline__ void cp_async16(uint32_t dst, const float* src, int srcBytes) {
    asm volatile("cp.async.cg.shared.global [%0], [%1], 16, %2;\n"
                 :: "r"(dst), "l"(src), "r"(srcBytes));
}
#define CP_COMMIT() asm volatile("cp.async.commit_group;\n" ::: "memory")
#define CP_WAIT(n)  asm volatile("cp.async.wait_group %0;\n" :: "n"(n) : "memory")

// ---------------- tf32 pre-round pass ----------------
__global__ void tf32_round_kernel(const float4* __restrict__ in,
                                  float4* __restrict__ out, int n4)
{
    const int i = blockIdx.x * blockDim.x + threadIdx.x;
    if (i < n4) {
        float4 v = in[i];
        out[i] = make_float4(tfr(v.x), tfr(v.y), tfr(v.z), tfr(v.w));
    }
}

// ---------------- tf32 GEMM, 3-stage cp.async, no inner-loop cvt ------------
// C[M,N] = A[M,K] @ B[K,N]. 128x128x32 tile, 256 thr (8 warps), warp 32x64.
// A,B must be pre-rounded to tf32. M%128==0, K%32==0, N guarded (N%4==0).
#define GA_WORDS 4608   // 128*36
#define GB_WORDS 4352   // 32*136
#define GSTAGE   (GA_WORDS + GB_WORDS)
#define GEMM_SMEM_BYTES (3 * GSTAGE * 4)

__global__ void __launch_bounds__(256)
gemm_tf32(const float* __restrict__ A, const float* __restrict__ Bm,
          float* __restrict__ C, int M, int N, int K, int rnd)
{
    extern __shared__ float gsm[];
    const uint32_t sbase = (uint32_t)__cvta_generic_to_shared(gsm);

    const int tid  = threadIdx.x;
    const int wid  = tid >> 5;
    const int lane = tid & 31;
    const int lr   = lane >> 2;
    const int lc   = lane & 3;
    const int wm   = wid & 3;
    const int wn   = wid >> 2;
    const int m0   = blockIdx.y * 128;
    const int n0   = blockIdx.x * 128;

    float acc[2][8][4];
#pragma unroll
    for (int i = 0; i < 2; i++)
#pragma unroll
        for (int j = 0; j < 8; j++)
#pragma unroll
            for (int k = 0; k < 4; k++) acc[i][j][k] = 0.f;

    auto loadTile = [&](int stage, int k0) {
        const uint32_t aB = sbase + stage * GSTAGE * 4;
        const uint32_t bB = aB + GA_WORDS * 4;
#pragma unroll
        for (int i = 0; i < 4; i++) {
            const int idx = tid + i * 256;
            const int m = idx >> 3, k4 = idx & 7;
            cp_async16(aB + (m * 36 + k4 * 4) * 4,
                       A + (size_t)(m0 + m) * K + k0 + k4 * 4, 16);
        }
#pragma unroll
        for (int i = 0; i < 4; i++) {
            const int idx = tid + i * 256;
            const int kk = idx >> 5, n4 = idx & 31;
            const int nc = n0 + n4 * 4;
            const float* src = Bm + (size_t)(k0 + kk) * N + (nc < N ? nc : N - 4);
            cp_async16(bB + (kk * 136 + n4 * 4) * 4, src, nc < N ? 16 : 0);
        }
    };

    const int T = K >> 5;
    loadTile(0, 0); CP_COMMIT();
    if (T > 1) { loadTile(1, 32); CP_COMMIT(); }

    for (int it = 0; it < T; it++) {
        if (it + 2 < T) { loadTile((it + 2) % 3, (it + 2) * 32); CP_COMMIT(); CP_WAIT(2); }
        else            { CP_WAIT(0); }
        __syncthreads();

        const float* Af = gsm + (it % 3) * GSTAGE;
        const float* Bf = Af + GA_WORDS;
#pragma unroll
        for (int ks = 0; ks < 4; ks++) {
            const int kb = ks * 8 + lc;
            unsigned a[2][4];
#pragma unroll
            for (int mt = 0; mt < 2; mt++) {
                const int mb = wm * 32 + mt * 16;
                a[mt][0] = __float_as_uint(Af[(mb + lr) * 36 + kb]);
                a[mt][1] = __float_as_uint(Af[(mb + lr + 8) * 36 + kb]);
                a[mt][2] = __float_as_uint(Af[(mb + lr) * 36 + kb + 4]);
                a[mt][3] = __float_as_uint(Af[(mb + lr + 8) * 36 + kb + 4]);
            }
#pragma unroll
            for (int nt = 0; nt < 8; nt++) {
                const int nb = wn * 64 + nt * 8 + lr;
                const unsigned b0 = __float_as_uint(Bf[kb * 136 + nb]);
                const unsigned b1 = __float_as_uint(Bf[(kb + 4) * 136 + nb]);
                mma8(acc[0][nt], a[0][0], a[0][1], a[0][2], a[0][3], b0, b1);
                mma8(acc[1][nt], a[1][0], a[1][1], a[1][2], a[1][3], b0, b1);
            }
        }
        __syncthreads();
    }

#pragma unroll
    for (int mt = 0; mt < 2; mt++)
#pragma unroll
        for (int nt = 0; nt < 8; nt++) {
            const int row = m0 + wm * 32 + mt * 16 + lr;
            const int col = n0 + wn * 64 + nt * 8 + 2 * lc;
            if (col < N) {
                float4 v = make_float4(acc[mt][nt][0], acc[mt][nt][1],
                                       acc[mt][nt][2], acc[mt][nt][3]);
                if (rnd) v = make_float4(tfr(v.x), tfr(v.y), tfr(v.z), tfr(v.w));
                *(float2*)(C + (size_t)row * N + col) = make_float2(v.x, v.y);
                *(float2*)(C + (size_t)(row + 8) * N + col) = make_float2(v.z, v.w);
            }
        }
}

// ---------------- prep: RMSNorm(c_kv), RoPE(k_rope), RoPE(q) -----------------
// Rounds all of its outputs (and q_nope in place) to tf32.
__global__ void prep_kernel(const float* __restrict__ w)
{
    const int row = blockIdx.x;
    const int s   = row % S_;
    const int tid = threadIdx.x;

    const float c0 = g_kva[(size_t)row * KVA_N + tid];
    const float c1 = g_kva[(size_t)row * KVA_N + tid + 256];
    float ss = c0 * c0 + c1 * c1;
#pragma unroll
    for (int o = 16; o > 0; o >>= 1) ss += __shfl_xor_sync(0xffffffffu, ss, o);
    __shared__ float red[8];
    if ((tid & 31) == 0) red[tid >> 5] = ss;
    __syncthreads();
    if (tid == 0) {
        float v = 0.f;
#pragma unroll
        for (int i = 0; i < 8; i++) v += red[i];
        red[0] = v;
    }
    __syncthreads();
    const float inv = rsqrtf(red[0] * (1.f / 512.f) + RMS_EPS);
    g_ckv[(size_t)row * DKVL + tid]       = tfr(c0 * inv * w[tid]);
    g_ckv[(size_t)row * DKVL + tid + 256] = tfr(c1 * inv * w[tid + 256]);

    if (tid < 32) {
        const float fr = expf(-(float)tid * ROPE_LC);
        const float t  = (float)s * fr;
        const float cs = cosf(t), sn = sinf(t);
        const float x1 = g_kva[(size_t)row * KVA_N + DKVL + 2 * tid];
        const float x2 = g_kva[(size_t)row * KVA_N + DKVL + 2 * tid + 1];
        g_kr[(size_t)row * DROPE + 2 * tid]     = tfr(x1 * cs - x2 * sn);
        g_kr[(size_t)row * DROPE + 2 * tid + 1] = tfr(x2 * cs + x1 * sn);
    }

    // rope q (rounds output)
    for (int p = tid; p < NH * 32; p += 256) {
        const int h = p >> 5, i = p & 31;
        const float fr = expf(-(float)i * ROPE_LC);
        const float t  = (float)s * fr;
        const float cs = cosf(t), sn = sinf(t);
        const size_t base = (size_t)row * HQ + h * DQKD + DNOPE + 2 * i;
        const float x1 = g_q[base], x2 = g_q[base + 1];
        g_q[base]     = tfr(x1 * cs - x2 * sn);
        g_q[base + 1] = tfr(x2 * cs + x1 * sn);
    }

    // round q_nope in place (tf32)
    for (int p = tid; p < NH * DNOPE / 4; p += 256) {
        const int h = p >> 5, d4 = p & 31;
        float4* ptr = (float4*)(g_q + (size_t)row * HQ + h * DQKD + d4 * 4);
        float4 v = *ptr;
        *ptr = make_float4(tfr(v.x), tfr(v.y), tfr(v.z), tfr(v.w));
    }
}

// ---------------- tensor-core flash attention (BM=128, BN=64) ----------------
// All inputs pre-rounded tf32; loads via cp.async, no cvt.
#define QS_STR 196
#define KS_STR 196
#define VS_STR 136
#define PS_STR 68

#define QS_OFF 0
#define KS_OFF (QS_OFF + 128 * QS_STR)
#define VS_OFF (KS_OFF + 64 * KS_STR)
#define PS_OFF (VS_OFF + 64 * VS_STR)
#define ATT_WORDS (PS_OFF + 128 * PS_STR)
#define ATT_BYTES (ATT_WORDS * 4)

__global__ void __launch_bounds__(256)
attn_tc()
{
    extern __shared__ unsigned sm[];
    unsigned* Qs = sm + QS_OFF;
    unsigned* Ks = sm + KS_OFF;
    unsigned* Vs = sm + VS_OFF;
    unsigned* Ps = sm + PS_OFF;
    const uint32_t sbase = (uint32_t)__cvta_generic_to_shared(sm);
    const uint32_t sQ = sbase + QS_OFF * 4;
    const uint32_t sK = sbase + KS_OFF * 4;
    const uint32_t sV = sbase + VS_OFF * 4;

    const int qblk = blockIdx.x;
    const int h    = blockIdx.y;
    const int b    = blockIdx.z;
    const int tid  = threadIdx.x;
    const int w    = tid >> 5;
    const int lane = tid & 31;
    const int lr   = lane >> 2;
    const int lc   = lane & 3;
    const int w16  = w * 16;
    const int q0   = qblk * 128;
    const int bS   = b * S_;

    const float scale = 0.07216878364870323f; // 1/sqrt(192)

    // ---- Q tile (128 x 192) via cp.async ----
#pragma unroll
    for (int i = 0; i < 24; i++) {
        const int idx = tid + i * 256;        // 6144 float4
        const int r = idx / 48, d4 = idx % 48;
        cp_async16(sQ + (r * QS_STR + d4 * 4) * 4,
                   g_q + (size_t)(bS + q0 + r) * HQ + h * DQKD + d4 * 4, 16);
    }
    CP_COMMIT();

    float oacc[16][4];
#pragma unroll
    for (int i = 0; i < 16; i++)
#pragma unroll
        for (int j = 0; j < 4; j++) oacc[i][j] = 0.f;
    float m0v = -1e30f, m1v = -1e30f, l0 = 0.f, l1 = 0.f;

    const int row0g = q0 + w16 + lr;
    const int row1g = row0g + 8;
    const int lastNeeded = q0 + w16 + 15;

    CP_WAIT(0);
    __syncthreads();

    const int ktMax = 2 * qblk + 1;
    for (int kt = 0; kt <= ktMax; kt++) {
        const int k0 = kt * 64;

        // K nope (2048 f4), K rope (1024 f4), V (2048 f4)
#pragma unroll
        for (int i = 0; i < 8; i++) {
            const int idx = tid + i * 256;
            const int j = idx >> 5, d4 = idx & 31;
            cp_async16(sK + (j * KS_STR + d4 * 4) * 4,
                       g_kvb + (size_t)(bS + k0 + j) * HKV + h * 256 + d4 * 4, 16);
        }
#pragma unroll
        for (int i = 0; i < 4; i++) {
            const int idx = tid + i * 256;
            const int j = idx >> 4, d4 = idx & 15;
            cp_async16(sK + (j * KS_STR + 128 + d4 * 4) * 4,
                       g_kr + (size_t)(bS + k0 + j) * DROPE + d4 * 4, 16);
        }
#pragma unroll
        for (int i = 0; i < 8; i++) {
            const int idx = tid + i * 256;
            const int j = idx >> 5, d4 = idx & 31;
            cp_async16(sV + (j * VS_STR + d4 * 4) * 4,
                       g_kvb + (size_t)(bS + k0 + j) * HKV + h * 256 + 128 + d4 * 4, 16);
        }
        CP_COMMIT();
        CP_WAIT(0);
        __syncthreads();

        if (k0 <= lastNeeded) {
            // ---- S = Q @ K^T ----
            float sacc[8][4];
#pragma unroll
            for (int i = 0; i < 8; i++)
#pragma unroll
                for (int j = 0; j < 4; j++) sacc[i][j] = 0.f;

#pragma unroll
            for (int ks = 0; ks < 24; ks++) {
                const int kb = ks * 8 + lc;
                const unsigned a0 = Qs[(w16 + lr) * QS_STR + kb];
                const unsigned a1 = Qs[(w16 + lr + 8) * QS_STR + kb];
                const unsigned a2 = Qs[(w16 + lr) * QS_STR + kb + 4];
                const unsigned a3 = Qs[(w16 + lr + 8) * QS_STR + kb + 4];
#pragma unroll
                for (int nt = 0; nt < 8; nt++) {
                    const unsigned b0 = Ks[(nt * 8 + lr) * KS_STR + kb];
                    const unsigned b1 = Ks[(nt * 8 + lr) * KS_STR + kb + 4];
                    mma8(sacc[nt], a0, a1, a2, a3, b0, b1);
                }
            }

            // ---- mask + scale, row max ----
            const bool domask = (k0 + 63 > q0 + w16);
            float mt0 = -1e30f, mt1 = -1e30f;
#pragma unroll
            for (int nt = 0; nt < 8; nt++) {
                const int jb = k0 + nt * 8 + 2 * lc;
#pragma unroll
                for (int c = 0; c < 4; c++) {
                    float s = sacc[nt][c] * scale;
                    const int jg = jb + (c & 1);
                    const int rg = (c < 2) ? row0g : row1g;
                    if (domask && jg > rg) s = -1e30f;
                    sacc[nt][c] = s;
                    if (c < 2) mt0 = fmaxf(mt0, s); else mt1 = fmaxf(mt1, s);
                }
            }
            mt0 = fmaxf(mt0, __shfl_xor_sync(0xffffffffu, mt0, 1));
            mt0 = fmaxf(mt0, __shfl_xor_sync(0xffffffffu, mt0, 2));
            mt1 = fmaxf(mt1, __shfl_xor_sync(0xffffffffu, mt1, 1));
            mt1 = fmaxf(mt1, __shfl_xor_sync(0xffffffffu, mt1, 2));

            const float mn0 = fmaxf(m0v, mt0);
            const float mn1 = fmaxf(m1v, mt1);
            const float al0 = __expf(m0v - mn0);
            const float al1 = __expf(m1v - mn1);
            m0v = mn0; m1v = mn1;

            // ---- P = exp(S - m) ----
            float rs0 = 0.f, rs1 = 0.f;
#pragma unroll
            for (int nt = 0; nt < 8; nt++) {
                const int jj = nt * 8 + 2 * lc;
                const float p0 = __expf(sacc[nt][0] - mn0);
                const float p1 = __expf(sacc[nt][1] - mn0);
                const float p2 = __expf(sacc[nt][2] - mn1);
                const float p3 = __expf(sacc[nt][3] - mn1);
                rs0 += p0 + p1; rs1 += p2 + p3;
                Ps[(w16 + lr) * PS_STR + jj]         = f2tf(p0);
                Ps[(w16 + lr) * PS_STR + jj + 1]     = f2tf(p1);
                Ps[(w16 + lr + 8) * PS_STR + jj]     = f2tf(p2);
                Ps[(w16 + lr + 8) * PS_STR + jj + 1] = f2tf(p3);
            }
            rs0 += __shfl_xor_sync(0xffffffffu, rs0, 1);
            rs0 += __shfl_xor_sync(0xffffffffu, rs0, 2);
            rs1 += __shfl_xor_sync(0xffffffffu, rs1, 1);
            rs1 += __shfl_xor_sync(0xffffffffu, rs1, 2);
            l0 = l0 * al0 + rs0;
            l1 = l1 * al1 + rs1;

            // ---- rescale O ----
#pragma unroll
            for (int nt = 0; nt < 16; nt++) {
                oacc[nt][0] *= al0; oacc[nt][1] *= al0;
                oacc[nt][2] *= al1; oacc[nt][3] *= al1;
            }
            __syncwarp();

            // ---- O += P @ V ----
#pragma unroll
            for (int ks = 0; ks < 8; ks++) {
                const int kb = ks * 8 + lc;
                const unsigned a0 = Ps[(w16 + lr) * PS_STR + kb];
                const unsigned a1 = Ps[(w16 + lr + 8) * PS_STR + kb];
                const unsigned a2 = Ps[(w16 + lr) * PS_STR + kb + 4];
                const unsigned a3 = Ps[(w16 + lr + 8) * PS_STR + kb + 4];
#pragma unroll
                for (int nt = 0; nt < 16; nt++) {
                    const unsigned b0 = Vs[kb * VS_STR + nt * 8 + lr];
                    const unsigned b1 = Vs[(kb + 4) * VS_STR + nt * 8 + lr];
                    mma8(oacc[nt], a0, a1, a2, a3, b0, b1);
                }
            }
        }
        __syncthreads();
    }

    // ---- normalize + write (rounded tf32 for Wo GEMM) ----
    const float inv0 = 1.f / l0;
    const float inv1 = 1.f / l1;
#pragma unroll
    for (int nt = 0; nt < 16; nt++) {
        const int col = h * DV + nt * 8 + 2 * lc;
        *(float2*)(g_att + (size_t)(bS + row0g) * (NH * DV) + col) =
            make_float2(tfr(oacc[nt][0] * inv0), tfr(oacc[nt][1] * inv0));
        *(float2*)(g_att + (size_t)(bS + row1g) * (NH * DV) + col) =
            make_float2(tfr(oacc[nt][2] * inv1), tfr(oacc[nt][3] * inv1));
    }
}

// ---------------- launch ----------------
extern "C" void kernel_launch(void* const* d_in, const int* in_sizes, int n_in,
                              void* d_out, int out_size)
{
    const float* x     = (const float*)d_in[0];
    const float* Wq    = (const float*)d_in[1];
    const float* Wkv_a = (const float*)d_in[2];
    const float* knw   = (const float*)d_in[3];
    const float* Wkv_b = (const float*)d_in[4];
    const float* Wo    = (const float*)d_in[5];
    float* out = (float*)d_out;

    static float *p_q, *p_kva, *p_ckv, *p_kvb, *p_att;
    static float *p_xr, *p_wq, *p_wkva, *p_wkvb, *p_wo;
    static bool init = false;
    if (!init) {
        cudaGetSymbolAddress((void**)&p_q,    g_q);
        cudaGetSymbolAddress((void**)&p_kva,  g_kva);
        cudaGetSymbolAddress((void**)&p_ckv,  g_ckv);
        cudaGetSymbolAddress((void**)&p_kvb,  g_kvb);
        cudaGetSymbolAddress((void**)&p_att,  g_att);
        cudaGetSymbolAddress((void**)&p_xr,   g_xr);
        cudaGetSymbolAddress((void**)&p_wq,   g_wq);
        cudaGetSymbolAddress((void**)&p_wkva, g_wkva);
        cudaGetSymbolAddress((void**)&p_wkvb, g_wkvb);
        cudaGetSymbolAddress((void**)&p_wo,   g_wo);
        cudaFuncSetAttribute(attn_tc,
                             cudaFuncAttributeMaxDynamicSharedMemorySize,
                             ATT_BYTES);
        cudaFuncSetAttribute(gemm_tf32,
                             cudaFuncAttributeMaxDynamicSharedMemorySize,
                             GEMM_SMEM_BYTES);
        init = true;
    }

    // ---- pre-round inputs to tf32 ----
    auto rnd = [&](const float* src, float* dst, int n) {
        const int n4 = n / 4;
        tf32_round_kernel<<<(n4 + 255) / 256, 256>>>((const float4*)src, (float4*)dst, n4);
    };
    rnd(x,     p_xr,   BS * DM);
    rnd(Wq,    p_wq,   DM * HQ);
    rnd(Wkv_a, p_wkva, DM * KVA_N);
    rnd(Wkv_b, p_wkvb, DKVL * HKV);
    rnd(Wo,    p_wo,   NH * DV * DM);

    const dim3 blk(256);
    gemm_tf32<<<dim3(HQ / 128, BS / 128), blk, GEMM_SMEM_BYTES>>>(p_xr, p_wq, p_q, BS, HQ, DM, 0);
    gemm_tf32<<<dim3((KVA_N + 127) / 128, BS / 128), blk, GEMM_SMEM_BYTES>>>(p_xr, p_wkva, p_kva, BS, KVA_N, DM, 0);
    prep_kernel<<<BS, 256>>>(knw);
    gemm_tf32<<<dim3(HKV / 128, BS / 128), blk, GEMM_SMEM_BYTES>>>(p_ckv, p_wkvb, p_kvb, BS, HKV, DKVL, 1);
    attn_tc<<<dim3(S_ / 128, NH, B_), 256, ATT_BYTES>>>();
    gemm_tf32<<<dim3(DM / 128, BS / 128), blk, GEMM_SMEM_BYTES>>>(p_att, p_wo, out, BS, DM, DM, 0);
}

// round 7
// speedup vs baseline: 7.8076x; 1.0600x over previous
#include <cuda_runtime.h>
#include <math.h>
#include <stdint.h>

// ---------------- problem dims ----------------
#define B_      2
#define S_      2048
#define DM      2048
#define NH      16
#define DNOPE   128
#define DROPE   64
#define DQKD    192
#define DKVL    512
#define DV      128
#define BS      (B_*S_)          // 4096
#define HQ      (NH*DQKD)        // 3072
#define HKV     (NH*(DNOPE+DV))  // 4096
#define KVA_N   (DKVL+DROPE)     // 576
#define RMS_EPS 1.1920928955078125e-07f
#define ROPE_LC 0.28782313662425572f   // ln(10000)/32

// ---------------- scratch ----------------
__device__ float g_q  [BS*HQ];
__device__ float g_kva[BS*KVA_N];
__device__ float g_ckv[BS*DKVL];
__device__ float g_kr [BS*DROPE];
__device__ float g_kvb[BS*HKV];
__device__ float g_att[BS*(NH*DV)];
// tf32-rounded activations / transposed+rounded weights (Bt[N][K], K-major)
__device__ float g_xr  [BS*DM];
__device__ float g_wqT [HQ*DM];
__device__ float g_wkvaT[KVA_N*DM];
__device__ float g_wkvbT[HKV*DKVL];
__device__ float g_woT [DM*NH*DV];

// ---------------- helpers ----------------
__device__ __forceinline__ unsigned f2tf(float f) {
    unsigned u;
    asm("cvt.rna.tf32.f32 %0, %1;" : "=r"(u) : "f"(f));
    return u;
}
__device__ __forceinline__ float tfr(float f) { return __uint_as_float(f2tf(f)); }

__device__ __forceinline__ void mma8(float* c, unsigned a0, unsigned a1,
                                     unsigned a2, unsigned a3,
                                     unsigned b0, unsigned b1) {
    asm volatile(
        "mma.sync.aligned.m16n8k8.row.col.f32.tf32.tf32.f32 "
        "{%0,%1,%2,%3},{%4,%5,%6,%7},{%8,%9},{%0,%1,%2,%3};\n"
        : "+f"(c[0]), "+f"(c[1]), "+f"(c[2]), "+f"(c[3])
        : "r"(a0), "r"(a1), "r"(a2), "r"(a3), "r"(b0), "r"(b1));
}

// ldmatrix x4: four 8-row x 16B tiles; lane group (lane>>3) selects the tile
__device__ __forceinline__ void ldsm4(unsigned* r, uint32_t addr) {
    asm volatile("ldmatrix.sync.aligned.m8n8.x4.shared.b16 {%0,%1,%2,%3}, [%4];"
                 : "=r"(r[0]), "=r"(r[1]), "=r"(r[2]), "=r"(r[3]) : "r"(addr));
}

__device__ __forceinline__ void cp_async16(uint32_t dst, const float* src, int srcBytes) {
    asm volatile("cp.async.cg.shared.global [%0], [%1], 16, %2;\n"
                 :: "r"(dst), "l"(src), "r"(srcBytes));
}
#define CP_COMMIT() asm volatile("cp.async.commit_group;\n" ::: "memory")
#define CP_WAIT(n)  asm volatile("cp.async.wait_group %0;\n" :: "n"(n) : "memory")

// ---------------- tf32 round (x) and transpose+round (weights) --------------
__global__ void tf32_round_kernel(const float4* __restrict__ in,
                                  float4* __restrict__ out, int n4)
{
    const int i = blockIdx.x * blockDim.x + threadIdx.x;
    if (i < n4) {
        float4 v = in[i];
        out[i] = make_float4(tfr(v.x), tfr(v.y), tfr(v.z), tfr(v.w));
    }
}

// in[R][C] -> out[C][R], rounded to tf32. R,C % 32 == 0. block (32,8).
__global__ void trT_kernel(const float* __restrict__ in, float* __restrict__ out,
                           int R, int Cc)
{
    __shared__ float t[32][33];
    const int c0 = blockIdx.x * 32, r0 = blockIdx.y * 32;
    const int tx = threadIdx.x, ty = threadIdx.y;
#pragma unroll
    for (int i = 0; i < 4; i++)
        t[ty + i * 8][tx] = in[(size_t)(r0 + ty + i * 8) * Cc + c0 + tx];
    __syncthreads();
#pragma unroll
    for (int i = 0; i < 4; i++)
        out[(size_t)(c0 + ty + i * 8) * R + r0 + tx] = tfr(t[tx][ty + i * 8]);
}

// ---------------- tf32 GEMM: C[M,N] = A[M,K] @ Bt[N,K]^T --------------------
// 128x128x32 tile, 256 thr (8 warps, wm 0..3 x wn 0..1), warp 32x64.
// A and Bt both k-major, pre-rounded tf32. Fragments via ldmatrix.
// A tile [128][36] words, B tile [128][36] words, 3-stage cp.async.
#define GTILE_W  (128 * 36)               // words per operand tile
#define GSTAGE_B (2 * GTILE_W * 4)        // bytes per stage (A + B)
#define GEMM_SMEM_BYTES (3 * GSTAGE_B)    // 110592

__global__ void __launch_bounds__(256)
gemm_tf32(const float* __restrict__ A, const float* __restrict__ Bt,
          float* __restrict__ C, int M, int N, int K, int rnd)
{
    extern __shared__ float gsm[];
    const uint32_t sb = (uint32_t)__cvta_generic_to_shared(gsm);

    const int tid  = threadIdx.x;
    const int wid  = tid >> 5;
    const int lane = tid & 31;
    const int lr   = lane >> 2;
    const int lc   = lane & 3;
    const int g    = lane >> 3;     // ldmatrix tile group 0..3
    const int l8   = lane & 7;
    const int wm   = wid & 3;
    const int wn   = wid >> 2;
    const int m0   = blockIdx.y * 128;
    const int n0   = blockIdx.x * 128;

    // per-lane ldmatrix base addresses (stage/ks/mt offsets added later)
    const uint32_t aBase = sb +
        (((wm * 32 + l8 + 8 * (g & 1)) * 36 + 4 * (g >> 1)) << 2);
    const uint32_t bBase = sb + GTILE_W * 4 +
        (((wn * 64 + l8 + 8 * (g >> 1)) * 36 + 4 * (g & 1)) << 2);

    float acc[2][8][4];
#pragma unroll
    for (int i = 0; i < 2; i++)
#pragma unroll
        for (int j = 0; j < 8; j++)
#pragma unroll
            for (int k = 0; k < 4; k++) acc[i][j][k] = 0.f;

    auto loadTile = [&](int stage, int kt) {
        const uint32_t s0 = sb + (uint32_t)stage * GSTAGE_B;
        const int kb = kt * 32;
#pragma unroll
        for (int i = 0; i < 4; i++) {
            const int idx = tid + i * 256;
            const int m = idx >> 3, k4 = idx & 7;
            cp_async16(s0 + ((m * 36 + k4 * 4) << 2),
                       A + (size_t)(m0 + m) * K + kb + k4 * 4, 16);
        }
#pragma unroll
        for (int i = 0; i < 4; i++) {
            const int idx = tid + i * 256;
            const int n = idx >> 3, k4 = idx & 7;
            const int ng = n0 + n;
            const int ngc = ng < N ? ng : 0;
            cp_async16(s0 + GTILE_W * 4 + ((n * 36 + k4 * 4) << 2),
                       Bt + (size_t)ngc * K + kb + k4 * 4, ng < N ? 16 : 0);
        }
        CP_COMMIT();
    };

    const int T = K >> 5;
    loadTile(0, 0);
    if (T > 1) loadTile(1, 1);

    for (int it = 0; it < T; it++) {
        if (it + 2 < T) { loadTile((it + 2) % 3, it + 2); CP_WAIT(2); }
        else            { CP_WAIT(0); }
        __syncthreads();

        const uint32_t st = (uint32_t)(it % 3) * GSTAGE_B;
#pragma unroll
        for (int ks = 0; ks < 4; ks++) {
            unsigned a[2][4];
            ldsm4(a[0], aBase + st + ks * 32);
            ldsm4(a[1], aBase + st + ks * 32 + 2304);   // +16 rows
            unsigned b[8][2];
#pragma unroll
            for (int p = 0; p < 4; p++) {
                unsigned bb[4];
                ldsm4(bb, bBase + st + ks * 32 + p * 2304);
                b[2 * p][0] = bb[0]; b[2 * p][1] = bb[1];
                b[2 * p + 1][0] = bb[2]; b[2 * p + 1][1] = bb[3];
            }
#pragma unroll
            for (int nt = 0; nt < 8; nt++) {
                mma8(acc[0][nt], a[0][0], a[0][1], a[0][2], a[0][3], b[nt][0], b[nt][1]);
                mma8(acc[1][nt], a[1][0], a[1][1], a[1][2], a[1][3], b[nt][0], b[nt][1]);
            }
        }
        __syncthreads();
    }

#pragma unroll
    for (int mt = 0; mt < 2; mt++)
#pragma unroll
        for (int nt = 0; nt < 8; nt++) {
            const int row = m0 + wm * 32 + mt * 16 + lr;
            const int col = n0 + wn * 64 + nt * 8 + 2 * lc;
            if (col < N) {
                float4 v = make_float4(acc[mt][nt][0], acc[mt][nt][1],
                                       acc[mt][nt][2], acc[mt][nt][3]);
                if (rnd) v = make_float4(tfr(v.x), tfr(v.y), tfr(v.z), tfr(v.w));
                *(float2*)(C + (size_t)row * N + col) = make_float2(v.x, v.y);
                *(float2*)(C + (size_t)(row + 8) * N + col) = make_float2(v.z, v.w);
            }
        }
}

// ---------------- prep: RMSNorm(c_kv), RoPE(k_rope), RoPE(q) -----------------
__global__ void prep_kernel(const float* __restrict__ w)
{
    const int row = blockIdx.x;
    const int s   = row % S_;
    const int tid = threadIdx.x;

    const float c0 = g_kva[(size_t)row * KVA_N + tid];
    const float c1 = g_kva[(size_t)row * KVA_N + tid + 256];
    float ss = c0 * c0 + c1 * c1;
#pragma unroll
    for (int o = 16; o > 0; o >>= 1) ss += __shfl_xor_sync(0xffffffffu, ss, o);
    __shared__ float red[8];
    if ((tid & 31) == 0) red[tid >> 5] = ss;
    __syncthreads();
    if (tid == 0) {
        float v = 0.f;
#pragma unroll
        for (int i = 0; i < 8; i++) v += red[i];
        red[0] = v;
    }
    __syncthreads();
    const float inv = rsqrtf(red[0] * (1.f / 512.f) + RMS_EPS);
    g_ckv[(size_t)row * DKVL + tid]       = tfr(c0 * inv * w[tid]);
    g_ckv[(size_t)row * DKVL + tid + 256] = tfr(c1 * inv * w[tid + 256]);

    if (tid < 32) {
        const float fr = expf(-(float)tid * ROPE_LC);
        const float t  = (float)s * fr;
        const float cs = cosf(t), sn = sinf(t);
        const float x1 = g_kva[(size_t)row * KVA_N + DKVL + 2 * tid];
        const float x2 = g_kva[(size_t)row * KVA_N + DKVL + 2 * tid + 1];
        g_kr[(size_t)row * DROPE + 2 * tid]     = tfr(x1 * cs - x2 * sn);
        g_kr[(size_t)row * DROPE + 2 * tid + 1] = tfr(x2 * cs + x1 * sn);
    }

    for (int p = tid; p < NH * 32; p += 256) {
        const int h = p >> 5, i = p & 31;
        const float fr = expf(-(float)i * ROPE_LC);
        const float t  = (float)s * fr;
        const float cs = cosf(t), sn = sinf(t);
        const size_t base = (size_t)row * HQ + h * DQKD + DNOPE + 2 * i;
        const float x1 = g_q[base], x2 = g_q[base + 1];
        g_q[base]     = tfr(x1 * cs - x2 * sn);
        g_q[base + 1] = tfr(x2 * cs + x1 * sn);
    }

    for (int p = tid; p < NH * DNOPE / 4; p += 256) {
        const int h = p >> 5, d4 = p & 31;
        float4* ptr = (float4*)(g_q + (size_t)row * HQ + h * DQKD + d4 * 4);
        float4 v = *ptr;
        *ptr = make_float4(tfr(v.x), tfr(v.y), tfr(v.z), tfr(v.w));
    }
}

// ---------------- tensor-core flash attention (BM=128, BN=64) ----------------
#define QS_STR 196
#define KS_STR 196
#define VS_STR 136
#define PS_STR 68

#define QS_OFF 0
#define KS_OFF (QS_OFF + 128 * QS_STR)
#define VS_OFF (KS_OFF + 64 * KS_STR)
#define PS_OFF (VS_OFF + 64 * VS_STR)
#define ATT_WORDS (PS_OFF + 128 * PS_STR)
#define ATT_BYTES (ATT_WORDS * 4)

__global__ void __launch_bounds__(256)
attn_tc()
{
    extern __shared__ unsigned sm[];
    unsigned* Vs = sm + VS_OFF;
    unsigned* Ps = sm + PS_OFF;
    const uint32_t sbase = (uint32_t)__cvta_generic_to_shared(sm);
    const uint32_t sQ = sbase + QS_OFF * 4;
    const uint32_t sK = sbase + KS_OFF * 4;
    const uint32_t sV = sbase + VS_OFF * 4;

    const int qblk = blockIdx.x;
    const int h    = blockIdx.y;
    const int b    = blockIdx.z;
    const int tid  = threadIdx.x;
    const int w    = tid >> 5;
    const int lane = tid & 31;
    const int lr   = lane >> 2;
    const int lc   = lane & 3;
    const int g    = lane >> 3;
    const int l8   = lane & 7;
    const int w16  = w * 16;
    const int q0   = qblk * 128;
    const int bS   = b * S_;

    const float scale = 0.07216878364870323f; // 1/sqrt(192)

    // ldmatrix bases
    const uint32_t qB = sQ + (((w16 + l8 + 8 * (g & 1)) * QS_STR + 4 * (g >> 1)) << 2);
    const uint32_t kB = sK + (((l8 + 8 * (g >> 1)) * KS_STR + 4 * (g & 1)) << 2);
    const uint32_t pB = sbase + PS_OFF * 4 +
        (((w16 + l8 + 8 * (g & 1)) * PS_STR + 4 * (g >> 1)) << 2);

#pragma unroll
    for (int i = 0; i < 24; i++) {
        const int idx = tid + i * 256;
        const int r = idx / 48, d4 = idx % 48;
        cp_async16(sQ + ((r * QS_STR + d4 * 4) << 2),
                   g_q + (size_t)(bS + q0 + r) * HQ + h * DQKD + d4 * 4, 16);
    }
    CP_COMMIT();

    float oacc[16][4];
#pragma unroll
    for (int i = 0; i < 16; i++)
#pragma unroll
        for (int j = 0; j < 4; j++) oacc[i][j] = 0.f;
    float m0v = -1e30f, m1v = -1e30f, l0 = 0.f, l1 = 0.f;

    const int row0g = q0 + w16 + lr;
    const int row1g = row0g + 8;
    const int lastNeeded = q0 + w16 + 15;

    CP_WAIT(0);
    __syncthreads();

    const int ktMax = 2 * qblk + 1;
    for (int kt = 0; kt <= ktMax; kt++) {
        const int k0 = kt * 64;

#pragma unroll
        for (int i = 0; i < 8; i++) {
            const int idx = tid + i * 256;
            const int j = idx >> 5, d4 = idx & 31;
            cp_async16(sK + ((j * KS_STR + d4 * 4) << 2),
                       g_kvb + (size_t)(bS + k0 + j) * HKV + h * 256 + d4 * 4, 16);
        }
#pragma unroll
        for (int i = 0; i < 4; i++) {
            const int idx = tid + i * 256;
            const int j = idx >> 4, d4 = idx & 15;
            cp_async16(sK + ((j * KS_STR + 128 + d4 * 4) << 2),
                       g_kr + (size_t)(bS + k0 + j) * DROPE + d4 * 4, 16);
        }
#pragma unroll
        for (int i = 0; i < 8; i++) {
            const int idx = tid + i * 256;
            const int j = idx >> 5, d4 = idx & 31;
            cp_async16(sV + ((j * VS_STR + d4 * 4) << 2),
                       g_kvb + (size_t)(bS + k0 + j) * HKV + h * 256 + 128 + d4 * 4, 16);
        }
        CP_COMMIT();
        CP_WAIT(0);
        __syncthreads();

        if (k0 <= lastNeeded) {
            // ---- S = Q @ K^T : ldmatrix fragments ----
            float sacc[8][4];
#pragma unroll
            for (int i = 0; i < 8; i++)
#pragma unroll
                for (int j = 0; j < 4; j++) sacc[i][j] = 0.f;

#pragma unroll
            for (int ks = 0; ks < 24; ks++) {
                unsigned a[4];
                ldsm4(a, qB + ks * 32);
#pragma unroll
                for (int p = 0; p < 4; p++) {
                    unsigned bb[4];
                    ldsm4(bb, kB + ks * 32 + p * (16 * KS_STR * 4));
                    mma8(sacc[2 * p],     a[0], a[1], a[2], a[3], bb[0], bb[1]);
                    mma8(sacc[2 * p + 1], a[0], a[1], a[2], a[3], bb[2], bb[3]);
                }
            }

            const bool domask = (k0 + 63 > q0 + w16);
            float mt0 = -1e30f, mt1 = -1e30f;
#pragma unroll
            for (int nt = 0; nt < 8; nt++) {
                const int jb = k0 + nt * 8 + 2 * lc;
#pragma unroll
                for (int c = 0; c < 4; c++) {
                    float s = sacc[nt][c] * scale;
                    const int jg = jb + (c & 1);
                    const int rg = (c < 2) ? row0g : row1g;
                    if (domask && jg > rg) s = -1e30f;
                    sacc[nt][c] = s;
                    if (c < 2) mt0 = fmaxf(mt0, s); else mt1 = fmaxf(mt1, s);
                }
            }
            mt0 = fmaxf(mt0, __shfl_xor_sync(0xffffffffu, mt0, 1));
            mt0 = fmaxf(mt0, __shfl_xor_sync(0xffffffffu, mt0, 2));
            mt1 = fmaxf(mt1, __shfl_xor_sync(0xffffffffu, mt1, 1));
            mt1 = fmaxf(mt1, __shfl_xor_sync(0xffffffffu, mt1, 2));

            const float mn0 = fmaxf(m0v, mt0);
            const float mn1 = fmaxf(m1v, mt1);
            const float al0 = __expf(m0v - mn0);
            const float al1 = __expf(m1v - mn1);
            m0v = mn0; m1v = mn1;

            float rs0 = 0.f, rs1 = 0.f;
#pragma unroll
            for (int nt = 0; nt < 8; nt++) {
                const int jj = nt * 8 + 2 * lc;
                const float p0 = __expf(sacc[nt][0] - mn0);
                const float p1 = __expf(sacc[nt][1] - mn0);
                const float p2 = __expf(sacc[nt][2] - mn1);
                const float p3 = __expf(sacc[nt][3] - mn1);
                rs0 += p0 + p1; rs1 += p2 + p3;
                Ps[(w16 + lr) * PS_STR + jj]         = f2tf(p0);
                Ps[(w16 + lr) * PS_STR + jj + 1]     = f2tf(p1);
                Ps[(w16 + lr + 8) * PS_STR + jj]     = f2tf(p2);
                Ps[(w16 + lr + 8) * PS_STR + jj + 1] = f2tf(p3);
            }
            rs0 += __shfl_xor_sync(0xffffffffu, rs0, 1);
            rs0 += __shfl_xor_sync(0xffffffffu, rs0, 2);
            rs1 += __shfl_xor_sync(0xffffffffu, rs1, 1);
            rs1 += __shfl_xor_sync(0xffffffffu, rs1, 2);
            l0 = l0 * al0 + rs0;
            l1 = l1 * al1 + rs1;

#pragma unroll
            for (int nt = 0; nt < 16; nt++) {
                oacc[nt][0] *= al0; oacc[nt][1] *= al0;
                oacc[nt][2] *= al1; oacc[nt][3] *= al1;
            }
            __syncwarp();

            // ---- O += P @ V : P via ldmatrix, V scalar LDS ----
#pragma unroll
            for (int ks = 0; ks < 8; ks++) {
                unsigned a[4];
                ldsm4(a, pB + ks * 32);
                const int kb = ks * 8 + lc;
#pragma unroll
                for (int nt = 0; nt < 16; nt++) {
                    const unsigned b0 = Vs[kb * VS_STR + nt * 8 + lr];
                    const unsigned b1 = Vs[(kb + 4) * VS_STR + nt * 8 + lr];
                    mma8(oacc[nt], a[0], a[1], a[2], a[3], b0, b1);
                }
            }
        }
        __syncthreads();
    }

    const float inv0 = 1.f / l0;
    const float inv1 = 1.f / l1;
#pragma unroll
    for (int nt = 0; nt < 16; nt++) {
        const int col = h * DV + nt * 8 + 2 * lc;
        *(float2*)(g_att + (size_t)(bS + row0g) * (NH * DV) + col) =
            make_float2(tfr(oacc[nt][0] * inv0), tfr(oacc[nt][1] * inv0));
        *(float2*)(g_att + (size_t)(bS + row1g) * (NH * DV) + col) =
            make_float2(tfr(oacc[nt][2] * inv1), tfr(oacc[nt][3] * inv1));
    }
}

// ---------------- launch ----------------
extern "C" void kernel_launch(void* const* d_in, const int* in_sizes, int n_in,
                              void* d_out, int out_size)
{
    const float* x     = (const float*)d_in[0];
    const float* Wq    = (const float*)d_in[1];
    const float* Wkv_a = (const float*)d_in[2];
    const float* knw   = (const float*)d_in[3];
    const float* Wkv_b = (const float*)d_in[4];
    const float* Wo    = (const float*)d_in[5];
    float* out = (float*)d_out;

    static float *p_q, *p_kva, *p_ckv, *p_kvb, *p_att;
    static float *p_xr, *p_wqT, *p_wkvaT, *p_wkvbT, *p_woT;
    static bool init = false;
    if (!init) {
        cudaGetSymbolAddress((void**)&p_q,     g_q);
        cudaGetSymbolAddress((void**)&p_kva,   g_kva);
        cudaGetSymbolAddress((void**)&p_ckv,   g_ckv);
        cudaGetSymbolAddress((void**)&p_kvb,   g_kvb);
        cudaGetSymbolAddress((void**)&p_att,   g_att);
        cudaGetSymbolAddress((void**)&p_xr,    g_xr);
        cudaGetSymbolAddress((void**)&p_wqT,   g_wqT);
        cudaGetSymbolAddress((void**)&p_wkvaT, g_wkvaT);
        cudaGetSymbolAddress((void**)&p_wkvbT, g_wkvbT);
        cudaGetSymbolAddress((void**)&p_woT,   g_woT);
        cudaFuncSetAttribute(attn_tc,
                             cudaFuncAttributeMaxDynamicSharedMemorySize, ATT_BYTES);
        cudaFuncSetAttribute(gemm_tf32,
                             cudaFuncAttributeMaxDynamicSharedMemorySize, GEMM_SMEM_BYTES);
        init = true;
    }

    // pre-round x; transpose+round weights to [N][K] (k-major)
    {
        const int n4 = BS * DM / 4;
        tf32_round_kernel<<<(n4 + 255) / 256, 256>>>((const float4*)x, (float4*)p_xr, n4);
    }
    const dim3 tb(32, 8);
    trT_kernel<<<dim3(HQ / 32, DM / 32), tb>>>(Wq,    p_wqT,   DM,   HQ);
    trT_kernel<<<dim3(KVA_N / 32, DM / 32), tb>>>(Wkv_a, p_wkvaT, DM,   KVA_N);
    trT_kernel<<<dim3(HKV / 32, DKVL / 32), tb>>>(Wkv_b, p_wkvbT, DKVL, HKV);
    trT_kernel<<<dim3(DM / 32, DM / 32), tb>>>(Wo,    p_woT,   DM,   DM);

    const dim3 blk(256);
    gemm_tf32<<<dim3(HQ / 128, BS / 128), blk, GEMM_SMEM_BYTES>>>(p_xr, p_wqT, p_q, BS, HQ, DM, 0);
    gemm_tf32<<<dim3((KVA_N + 127) / 128, BS / 128), blk, GEMM_SMEM_BYTES>>>(p_xr, p_wkvaT, p_kva, BS, KVA_N, DM, 0);
    prep_kernel<<<BS, 256>>>(knw);
    gemm_tf32<<<dim3(HKV / 128, BS / 128), blk, GEMM_SMEM_BYTES>>>(p_ckv, p_wkvbT, p_kvb, BS, HKV, DKVL, 1);
    attn_tc<<<dim3(S_ / 128, NH, B_), 256, ATT_BYTES>>>();
    gemm_tf32<<<dim3(DM / 128, BS / 128), blk, GEMM_SMEM_BYTES>>>(p_att, p_woT, out, BS, DM, DM, 0);
}

// round 8
// speedup vs baseline: 14.1948x; 1.8181x over previous
#include <cuda_runtime.h>
#include <cuda_fp16.h>
#include <math.h>
#include <stdint.h>

// ---------------- problem dims ----------------
#define B_      2
#define S_      2048
#define DM      2048
#define NH      16
#define DNOPE   128
#define DROPE   64
#define DQKD    192
#define DKVL    512
#define DV      128
#define BS      (B_*S_)          // 4096
#define HQ      (NH*DQKD)        // 3072
#define HKV     (NH*(DNOPE+DV))  // 4096
#define KVA_N   (DKVL+DROPE)     // 576
#define RMS_EPS 1.1920928955078125e-07f
#define ROPE_LC 0.28782313662425572f   // ln(10000)/32

// ---------------- scratch (fp16 pipeline) ----------------
__device__ alignas(16) __half g_qh  [BS*HQ];
__device__ alignas(16) __half g_kvah[BS*KVA_N];
__device__ alignas(16) __half g_ckvh[BS*DKVL];
__device__ alignas(16) __half g_krh [BS*DROPE];
__device__ alignas(16) __half g_kvbh[BS*HKV];
__device__ alignas(16) __half g_atth[BS*(NH*DV)];
__device__ alignas(16) __half g_xh  [BS*DM];
__device__ alignas(16) __half g_wqTh [HQ*DM];
__device__ alignas(16) __half g_wkvaTh[KVA_N*DM];
__device__ alignas(16) __half g_wkvbTh[HKV*DKVL];
__device__ alignas(16) __half g_woTh [DM*NH*DV];

// ---------------- helpers ----------------
__device__ __forceinline__ void mma16(float* c, const unsigned* a,
                                      unsigned b0, unsigned b1) {
    asm volatile(
        "mma.sync.aligned.m16n8k16.row.col.f32.f16.f16.f32 "
        "{%0,%1,%2,%3},{%4,%5,%6,%7},{%8,%9},{%0,%1,%2,%3};\n"
        : "+f"(c[0]), "+f"(c[1]), "+f"(c[2]), "+f"(c[3])
        : "r"(a[0]), "r"(a[1]), "r"(a[2]), "r"(a[3]), "r"(b0), "r"(b1));
}

__device__ __forceinline__ void ldsm4(unsigned* r, uint32_t addr) {
    asm volatile("ldmatrix.sync.aligned.m8n8.x4.shared.b16 {%0,%1,%2,%3}, [%4];"
                 : "=r"(r[0]), "=r"(r[1]), "=r"(r[2]), "=r"(r[3]) : "r"(addr));
}
__device__ __forceinline__ void ldsm4t(unsigned* r, uint32_t addr) {
    asm volatile("ldmatrix.sync.aligned.m8n8.x4.trans.shared.b16 {%0,%1,%2,%3}, [%4];"
                 : "=r"(r[0]), "=r"(r[1]), "=r"(r[2]), "=r"(r[3]) : "r"(addr));
}

__device__ __forceinline__ void cp_async16(uint32_t dst, const void* src, int srcBytes) {
    asm volatile("cp.async.cg.shared.global [%0], [%1], 16, %2;\n"
                 :: "r"(dst), "l"(src), "r"(srcBytes));
}
#define CP_COMMIT() asm volatile("cp.async.commit_group;\n" ::: "memory")
#define CP_WAIT(n)  asm volatile("cp.async.wait_group %0;\n" :: "n"(n) : "memory")

// ---------------- fp32 -> fp16 conversion passes ----------------
__global__ void f2h_kernel(const float4* __restrict__ in,
                           __half2* __restrict__ out, int n4)
{
    const int i = blockIdx.x * blockDim.x + threadIdx.x;
    if (i < n4) {
        const float4 v = in[i];
        out[2 * i]     = __floats2half2_rn(v.x, v.y);
        out[2 * i + 1] = __floats2half2_rn(v.z, v.w);
    }
}

// in[R][C] fp32 -> out[C][R] fp16. R,C % 32 == 0. block (32,8).
__global__ void trTh_kernel(const float* __restrict__ in, __half* __restrict__ out,
                            int R, int Cc)
{
    __shared__ float t[32][33];
    const int c0 = blockIdx.x * 32, r0 = blockIdx.y * 32;
    const int tx = threadIdx.x, ty = threadIdx.y;
#pragma unroll
    for (int i = 0; i < 4; i++)
        t[ty + i * 8][tx] = in[(size_t)(r0 + ty + i * 8) * Cc + c0 + tx];
    __syncthreads();
#pragma unroll
    for (int i = 0; i < 4; i++)
        out[(size_t)(c0 + ty + i * 8) * R + r0 + tx] = __float2half_rn(t[tx][ty + i * 8]);
}

// ---------------- fp16 GEMM: C[M,N] = A[M,K] @ Bt[N,K]^T --------------------
// 128x128x64 tile, 256 thr (8 warps: wm 0..3 x wn 0..1), warp 32x64.
// A,Bt fp16 k-major. 3-stage cp.async. Row stride 72 halves (36 words ≡ 4 mod 32).
#define GASTRH   72
#define GTILE_B  (128 * GASTRH * 2)     // 18432 bytes per operand tile
#define GSTAGE_B (2 * GTILE_B)
#define GEMM_SMEM_BYTES (3 * GSTAGE_B)  // 110592

__global__ void __launch_bounds__(256)
gemm_h(const __half* __restrict__ A, const __half* __restrict__ Bt,
       void* __restrict__ C, int M, int N, int K, int outHalf)
{
    extern __shared__ __half hsm[];
    const uint32_t sb = (uint32_t)__cvta_generic_to_shared(hsm);

    const int tid  = threadIdx.x;
    const int wid  = tid >> 5;
    const int lane = tid & 31;
    const int lr   = lane >> 2;
    const int lc   = lane & 3;
    const int g    = lane >> 3;
    const int l8   = lane & 7;
    const int wm   = wid & 3;
    const int wn   = wid >> 2;
    const int m0   = blockIdx.y * 128;
    const int n0   = blockIdx.x * 128;

    const uint32_t aBase = sb + (((wm * 32 + l8 + 8 * (g & 1)) * GASTRH + 8 * (g >> 1)) << 1);
    const uint32_t bBase = sb + GTILE_B +
                           (((wn * 64 + l8 + 8 * (g >> 1)) * GASTRH + 8 * (g & 1)) << 1);

    float acc[2][8][4];
#pragma unroll
    for (int i = 0; i < 2; i++)
#pragma unroll
        for (int j = 0; j < 8; j++)
#pragma unroll
            for (int k = 0; k < 4; k++) acc[i][j][k] = 0.f;

    auto loadTile = [&](int stage, int kt) {
        const uint32_t s0 = sb + (uint32_t)stage * GSTAGE_B;
        const int kb = kt * 64;
#pragma unroll
        for (int i = 0; i < 4; i++) {
            const int idx = tid + i * 256;
            const int row = idx >> 3, c8 = idx & 7;
            cp_async16(s0 + ((row * GASTRH + c8 * 8) << 1),
                       A + (size_t)(m0 + row) * K + kb + c8 * 8, 16);
        }
#pragma unroll
        for (int i = 0; i < 4; i++) {
            const int idx = tid + i * 256;
            const int n = idx >> 3, c8 = idx & 7;
            const int ng = n0 + n;
            const int ngc = ng < N ? ng : 0;
            cp_async16(s0 + GTILE_B + ((n * GASTRH + c8 * 8) << 1),
                       Bt + (size_t)ngc * K + kb + c8 * 8, ng < N ? 16 : 0);
        }
        CP_COMMIT();
    };

    const int T = K >> 6;
    loadTile(0, 0);
    if (T > 1) loadTile(1, 1);

    for (int it = 0; it < T; it++) {
        if (it + 2 < T) { loadTile((it + 2) % 3, it + 2); CP_WAIT(2); }
        else            { CP_WAIT(0); }
        __syncthreads();

        const uint32_t st = (uint32_t)(it % 3) * GSTAGE_B;
#pragma unroll
        for (int ks = 0; ks < 4; ks++) {
            unsigned a[2][4];
            ldsm4(a[0], aBase + st + ks * 32);
            ldsm4(a[1], aBase + st + ks * 32 + 16 * GASTRH * 2);
            unsigned b[8][2];
#pragma unroll
            for (int p = 0; p < 4; p++) {
                unsigned bb[4];
                ldsm4(bb, bBase + st + ks * 32 + p * (16 * GASTRH * 2));
                b[2 * p][0] = bb[0]; b[2 * p][1] = bb[1];
                b[2 * p + 1][0] = bb[2]; b[2 * p + 1][1] = bb[3];
            }
#pragma unroll
            for (int nt = 0; nt < 8; nt++) {
                mma16(acc[0][nt], a[0], b[nt][0], b[nt][1]);
                mma16(acc[1][nt], a[1], b[nt][0], b[nt][1]);
            }
        }
        __syncthreads();
    }

#pragma unroll
    for (int mt = 0; mt < 2; mt++)
#pragma unroll
        for (int nt = 0; nt < 8; nt++) {
            const int row = m0 + wm * 32 + mt * 16 + lr;
            const int col = n0 + wn * 64 + nt * 8 + 2 * lc;
            if (col < N) {
                if (outHalf) {
                    *(__half2*)((__half*)C + (size_t)row * N + col) =
                        __floats2half2_rn(acc[mt][nt][0], acc[mt][nt][1]);
                    *(__half2*)((__half*)C + (size_t)(row + 8) * N + col) =
                        __floats2half2_rn(acc[mt][nt][2], acc[mt][nt][3]);
                } else {
                    *(float2*)((float*)C + (size_t)row * N + col) =
                        make_float2(acc[mt][nt][0], acc[mt][nt][1]);
                    *(float2*)((float*)C + (size_t)(row + 8) * N + col) =
                        make_float2(acc[mt][nt][2], acc[mt][nt][3]);
                }
            }
        }
}

// ---------------- prep: RMSNorm(c_kv), RoPE(k_rope), RoPE(q) -----------------
__global__ void prep_kernel(const float* __restrict__ w)
{
    const int row = blockIdx.x;
    const int s   = row % S_;
    const int tid = threadIdx.x;
    const __half* kva = g_kvah + (size_t)row * KVA_N;

    const float c0 = __half2float(kva[tid]);
    const float c1 = __half2float(kva[tid + 256]);
    float ss = c0 * c0 + c1 * c1;
#pragma unroll
    for (int o = 16; o > 0; o >>= 1) ss += __shfl_xor_sync(0xffffffffu, ss, o);
    __shared__ float red[8];
    if ((tid & 31) == 0) red[tid >> 5] = ss;
    __syncthreads();
    if (tid == 0) {
        float v = 0.f;
#pragma unroll
        for (int i = 0; i < 8; i++) v += red[i];
        red[0] = v;
    }
    __syncthreads();
    const float inv = rsqrtf(red[0] * (1.f / 512.f) + RMS_EPS);
    g_ckvh[(size_t)row * DKVL + tid]       = __float2half_rn(c0 * inv * w[tid]);
    g_ckvh[(size_t)row * DKVL + tid + 256] = __float2half_rn(c1 * inv * w[tid + 256]);

    if (tid < 32) {
        const float fr = expf(-(float)tid * ROPE_LC);
        const float t  = (float)s * fr;
        const float cs = cosf(t), sn = sinf(t);
        const float x1 = __half2float(kva[DKVL + 2 * tid]);
        const float x2 = __half2float(kva[DKVL + 2 * tid + 1]);
        *(__half2*)(g_krh + (size_t)row * DROPE + 2 * tid) =
            __floats2half2_rn(x1 * cs - x2 * sn, x2 * cs + x1 * sn);
    }

    for (int p = tid; p < NH * 32; p += 256) {
        const int h = p >> 5, i = p & 31;
        const float fr = expf(-(float)i * ROPE_LC);
        const float t  = (float)s * fr;
        const float cs = cosf(t), sn = sinf(t);
        __half2* qp = (__half2*)(g_qh + (size_t)row * HQ + h * DQKD + DNOPE + 2 * i);
        const __half2 v = *qp;
        const float x1 = __half2float(v.x), x2 = __half2float(v.y);
        *qp = __floats2half2_rn(x1 * cs - x2 * sn, x2 * cs + x1 * sn);
    }
}

// ---------------- fp16 tensor-core flash attention (BM=128, BN=64) -----------
#define QS_STRH 200   // 100 words ≡ 4 mod 32
#define KS_STRH 200
#define VS_STRH 136   // 68 words ≡ 4
#define PS_STRH 72    // 36 words ≡ 4

#define QS_OFFH 0
#define KS_OFFH (128 * QS_STRH)            // 25600
#define VS_OFFH (KS_OFFH + 64 * KS_STRH)   // 38400
#define PS_OFFH (VS_OFFH + 64 * VS_STRH)   // 47104
#define ATT_HALVES (PS_OFFH + 128 * PS_STRH)
#define ATT_BYTES (ATT_HALVES * 2)         // 112640

__global__ void __launch_bounds__(256, 2)
attn_tc()
{
    extern __shared__ __half asm_[];
    __half* Ps = asm_ + PS_OFFH;
    const uint32_t sbase = (uint32_t)__cvta_generic_to_shared(asm_);
    const uint32_t sQ = sbase;
    const uint32_t sK = sbase + KS_OFFH * 2;
    const uint32_t sV = sbase + VS_OFFH * 2;
    const uint32_t sP = sbase + PS_OFFH * 2;

    const int qblk = blockIdx.x;
    const int h    = blockIdx.y;
    const int b    = blockIdx.z;
    const int tid  = threadIdx.x;
    const int w    = tid >> 5;
    const int lane = tid & 31;
    const int lr   = lane >> 2;
    const int lc   = lane & 3;
    const int g    = lane >> 3;
    const int l8   = lane & 7;
    const int w16  = w * 16;
    const int q0   = qblk * 128;
    const int bS   = b * S_;

    const float scale = 0.07216878364870323f; // 1/sqrt(192)

    // fragment base addresses
    const uint32_t qB = sQ + (((w16 + l8 + 8 * (g & 1)) * QS_STRH + 8 * (g >> 1)) << 1);
    const uint32_t kB = sK + (((l8 + 8 * (g >> 1)) * KS_STRH + 8 * (g & 1)) << 1);
    const uint32_t pA = sP + (((w16 + l8 + 8 * (g & 1)) * PS_STRH + 8 * (g >> 1)) << 1);
    const uint32_t vB = sV + (((l8 + 8 * (g & 1)) * VS_STRH + 8 * (g >> 1)) << 1);

    // ---- Q tile: 128 rows x 192 halves (24 16B-chunks/row) ----
#pragma unroll
    for (int i = 0; i < 12; i++) {
        const int idx = tid + i * 256;
        const int r = idx / 24, c8 = idx % 24;
        cp_async16(sQ + ((r * QS_STRH + c8 * 8) << 1),
                   g_qh + (size_t)(bS + q0 + r) * HQ + h * DQKD + c8 * 8, 16);
    }
    CP_COMMIT();

    float oacc[16][4];
#pragma unroll
    for (int i = 0; i < 16; i++)
#pragma unroll
        for (int j = 0; j < 4; j++) oacc[i][j] = 0.f;
    float m0v = -1e30f, m1v = -1e30f, l0 = 0.f, l1 = 0.f;

    const int row0g = q0 + w16 + lr;
    const int row1g = row0g + 8;
    const int lastNeeded = q0 + w16 + 15;

    CP_WAIT(0);
    __syncthreads();

    const int ktMax = 2 * qblk + 1;
    for (int kt = 0; kt <= ktMax; kt++) {
        const int k0 = kt * 64;

        // K nope: 64 x 128 halves (16 chunks/row)
#pragma unroll
        for (int i = 0; i < 4; i++) {
            const int idx = tid + i * 256;
            const int j = idx >> 4, c8 = idx & 15;
            cp_async16(sK + ((j * KS_STRH + c8 * 8) << 1),
                       g_kvbh + (size_t)(bS + k0 + j) * HKV + h * 256 + c8 * 8, 16);
        }
        // K rope: 64 x 64 halves
#pragma unroll
        for (int i = 0; i < 2; i++) {
            const int idx = tid + i * 256;
            const int j = idx >> 3, c8 = idx & 7;
            cp_async16(sK + ((j * KS_STRH + 128 + c8 * 8) << 1),
                       g_krh + (size_t)(bS + k0 + j) * DROPE + c8 * 8, 16);
        }
        // V: 64 x 128 halves
#pragma unroll
        for (int i = 0; i < 4; i++) {
            const int idx = tid + i * 256;
            const int j = idx >> 4, c8 = idx & 15;
            cp_async16(sV + ((j * VS_STRH + c8 * 8) << 1),
                       g_kvbh + (size_t)(bS + k0 + j) * HKV + h * 256 + 128 + c8 * 8, 16);
        }
        CP_COMMIT();
        CP_WAIT(0);
        __syncthreads();

        if (k0 <= lastNeeded) {
            // ---- S = Q @ K^T : 12 k16-steps ----
            float sacc[8][4];
#pragma unroll
            for (int i = 0; i < 8; i++)
#pragma unroll
                for (int j = 0; j < 4; j++) sacc[i][j] = 0.f;

#pragma unroll
            for (int ks = 0; ks < 12; ks++) {
                unsigned a[4];
                ldsm4(a, qB + ks * 32);
#pragma unroll
                for (int p = 0; p < 4; p++) {
                    unsigned bb[4];
                    ldsm4(bb, kB + ks * 32 + p * (16 * KS_STRH * 2));
                    mma16(sacc[2 * p],     a, bb[0], bb[1]);
                    mma16(sacc[2 * p + 1], a, bb[2], bb[3]);
                }
            }

            // ---- mask + scale, row max ----
            const bool domask = (k0 + 63 > q0 + w16);
            float mt0 = -1e30f, mt1 = -1e30f;
#pragma unroll
            for (int nt = 0; nt < 8; nt++) {
                const int jb = k0 + nt * 8 + 2 * lc;
#pragma unroll
                for (int c = 0; c < 4; c++) {
                    float s = sacc[nt][c] * scale;
                    const int jg = jb + (c & 1);
                    const int rg = (c < 2) ? row0g : row1g;
                    if (domask && jg > rg) s = -1e30f;
                    sacc[nt][c] = s;
                    if (c < 2) mt0 = fmaxf(mt0, s); else mt1 = fmaxf(mt1, s);
                }
            }
            mt0 = fmaxf(mt0, __shfl_xor_sync(0xffffffffu, mt0, 1));
            mt0 = fmaxf(mt0, __shfl_xor_sync(0xffffffffu, mt0, 2));
            mt1 = fmaxf(mt1, __shfl_xor_sync(0xffffffffu, mt1, 1));
            mt1 = fmaxf(mt1, __shfl_xor_sync(0xffffffffu, mt1, 2));

            const float mn0 = fmaxf(m0v, mt0);
            const float mn1 = fmaxf(m1v, mt1);
            const float al0 = __expf(m0v - mn0);
            const float al1 = __expf(m1v - mn1);
            m0v = mn0; m1v = mn1;

            // ---- P = exp(S - m) -> fp16 smem; row sums ----
            float rs0 = 0.f, rs1 = 0.f;
#pragma unroll
            for (int nt = 0; nt < 8; nt++) {
                const int jj = nt * 8 + 2 * lc;
                const float p0 = __expf(sacc[nt][0] - mn0);
                const float p1 = __expf(sacc[nt][1] - mn0);
                const float p2 = __expf(sacc[nt][2] - mn1);
                const float p3 = __expf(sacc[nt][3] - mn1);
                rs0 += p0 + p1; rs1 += p2 + p3;
                *(__half2*)(Ps + (w16 + lr) * PS_STRH + jj)     = __floats2half2_rn(p0, p1);
                *(__half2*)(Ps + (w16 + lr + 8) * PS_STRH + jj) = __floats2half2_rn(p2, p3);
            }
            rs0 += __shfl_xor_sync(0xffffffffu, rs0, 1);
            rs0 += __shfl_xor_sync(0xffffffffu, rs0, 2);
            rs1 += __shfl_xor_sync(0xffffffffu, rs1, 1);
            rs1 += __shfl_xor_sync(0xffffffffu, rs1, 2);
            l0 = l0 * al0 + rs0;
            l1 = l1 * al1 + rs1;

            // ---- rescale O ----
#pragma unroll
            for (int nt = 0; nt < 16; nt++) {
                oacc[nt][0] *= al0; oacc[nt][1] *= al0;
                oacc[nt][2] *= al1; oacc[nt][3] *= al1;
            }
            __syncwarp();

            // ---- O += P @ V : 4 k16-steps, V via ldmatrix.trans ----
#pragma unroll
            for (int ks = 0; ks < 4; ks++) {
                unsigned a[4];
                ldsm4(a, pA + ks * 32);
#pragma unroll
                for (int p = 0; p < 8; p++) {
                    unsigned bb[4];
                    ldsm4t(bb, vB + ks * (16 * VS_STRH * 2) + p * 32);
                    mma16(oacc[2 * p],     a, bb[0], bb[1]);
                    mma16(oacc[2 * p + 1], a, bb[2], bb[3]);
                }
            }
        }
        __syncthreads();
    }

    // ---- normalize + write fp16 ----
    const float inv0 = 1.f / l0;
    const float inv1 = 1.f / l1;
#pragma unroll
    for (int nt = 0; nt < 16; nt++) {
        const int col = h * DV + nt * 8 + 2 * lc;
        *(__half2*)(g_atth + (size_t)(bS + row0g) * (NH * DV) + col) =
            __floats2half2_rn(oacc[nt][0] * inv0, oacc[nt][1] * inv0);
        *(__half2*)(g_atth + (size_t)(bS + row1g) * (NH * DV) + col) =
            __floats2half2_rn(oacc[nt][2] * inv1, oacc[nt][3] * inv1);
    }
}

// ---------------- launch ----------------
extern "C" void kernel_launch(void* const* d_in, const int* in_sizes, int n_in,
                              void* d_out, int out_size)
{
    const float* x     = (const float*)d_in[0];
    const float* Wq    = (const float*)d_in[1];
    const float* Wkv_a = (const float*)d_in[2];
    const float* knw   = (const float*)d_in[3];
    const float* Wkv_b = (const float*)d_in[4];
    const float* Wo    = (const float*)d_in[5];
    float* out = (float*)d_out;

    static __half *p_qh, *p_kvah, *p_ckvh, *p_kvbh, *p_atth;
    static __half *p_xh, *p_wqTh, *p_wkvaTh, *p_wkvbTh, *p_woTh;
    static bool init = false;
    if (!init) {
        cudaGetSymbolAddress((void**)&p_qh,     g_qh);
        cudaGetSymbolAddress((void**)&p_kvah,   g_kvah);
        cudaGetSymbolAddress((void**)&p_ckvh,   g_ckvh);
        cudaGetSymbolAddress((void**)&p_kvbh,   g_kvbh);
        cudaGetSymbolAddress((void**)&p_atth,   g_atth);
        cudaGetSymbolAddress((void**)&p_xh,     g_xh);
        cudaGetSymbolAddress((void**)&p_wqTh,   g_wqTh);
        cudaGetSymbolAddress((void**)&p_wkvaTh, g_wkvaTh);
        cudaGetSymbolAddress((void**)&p_wkvbTh, g_wkvbTh);
        cudaGetSymbolAddress((void**)&p_woTh,   g_woTh);
        cudaFuncSetAttribute(attn_tc,
                             cudaFuncAttributeMaxDynamicSharedMemorySize, ATT_BYTES);
        cudaFuncSetAttribute(gemm_h,
                             cudaFuncAttributeMaxDynamicSharedMemorySize, GEMM_SMEM_BYTES);
        init = true;
    }

    // convert x; transpose+convert weights to fp16 [N][K]
    {
        const int n4 = BS * DM / 4;
        f2h_kernel<<<(n4 + 255) / 256, 256>>>((const float4*)x, (__half2*)p_xh, n4);
    }
    const dim3 tb(32, 8);
    trTh_kernel<<<dim3(HQ / 32, DM / 32), tb>>>(Wq,    p_wqTh,   DM,   HQ);
    trTh_kernel<<<dim3(KVA_N / 32, DM / 32), tb>>>(Wkv_a, p_wkvaTh, DM,   KVA_N);
    trTh_kernel<<<dim3(HKV / 32, DKVL / 32), tb>>>(Wkv_b, p_wkvbTh, DKVL, HKV);
    trTh_kernel<<<dim3(DM / 32, DM / 32), tb>>>(Wo,    p_woTh,   DM,   DM);

    const dim3 blk(256);
    gemm_h<<<dim3(HQ / 128, BS / 128), blk, GEMM_SMEM_BYTES>>>(p_xh, p_wqTh, p_qh, BS, HQ, DM, 1);
    gemm_h<<<dim3((KVA_N + 127) / 128, BS / 128), blk, GEMM_SMEM_BYTES>>>(p_xh, p_wkvaTh, p_kvah, BS, KVA_N, DM, 1);
    prep_kernel<<<BS, 256>>>(knw);
    gemm_h<<<dim3(HKV / 128, BS / 128), blk, GEMM_SMEM_BYTES>>>(p_ckvh, p_wkvbTh, p_kvbh, BS, HKV, DKVL, 1);
    attn_tc<<<dim3(S_ / 128, NH, B_), 256, ATT_BYTES>>>();
    gemm_h<<<dim3(DM / 128, BS / 128), blk, GEMM_SMEM_BYTES>>>(p_atth, p_woTh, out, BS, DM, DM, 0);
}

// round 9
// speedup vs baseline: 14.2454x; 1.0036x over previous
#include <cuda_runtime.h>
#include <cuda_fp16.h>
#include <math.h>
#include <stdint.h>

// ---------------- problem dims ----------------
#define B_      2
#define S_      2048
#define DM      2048
#define NH      16
#define DNOPE   128
#define DROPE   64
#define DQKD    192
#define DKVL    512
#define DV      128
#define BS      (B_*S_)          // 4096
#define HQ      (NH*DQKD)        // 3072
#define HKV     (NH*(DNOPE+DV))  // 4096
#define KVA_N   (DKVL+DROPE)     // 576
#define RMS_EPS 1.1920928955078125e-07f
#define ROPE_LC 0.28782313662425572f   // ln(10000)/32

// ---------------- scratch (fp16 pipeline) ----------------
__device__ alignas(16) __half g_qh  [BS*HQ];
__device__ alignas(16) __half g_kvah[BS*KVA_N];
__device__ alignas(16) __half g_ckvh[BS*DKVL];
__device__ alignas(16) __half g_krh [BS*DROPE];
__device__ alignas(16) __half g_kvbh[BS*HKV];
__device__ alignas(16) __half g_atth[BS*(NH*DV)];
__device__ alignas(16) __half g_xh  [BS*DM];
__device__ alignas(16) __half g_wqTh [HQ*DM];
__device__ alignas(16) __half g_wkvaTh[KVA_N*DM];
__device__ alignas(16) __half g_wkvbTh[HKV*DKVL];
__device__ alignas(16) __half g_woTh [DM*NH*DV];

// ---------------- helpers ----------------
__device__ __forceinline__ void mma16(float* c, const unsigned* a,
                                      unsigned b0, unsigned b1) {
    asm volatile(
        "mma.sync.aligned.m16n8k16.row.col.f32.f16.f16.f32 "
        "{%0,%1,%2,%3},{%4,%5,%6,%7},{%8,%9},{%0,%1,%2,%3};\n"
        : "+f"(c[0]), "+f"(c[1]), "+f"(c[2]), "+f"(c[3])
        : "r"(a[0]), "r"(a[1]), "r"(a[2]), "r"(a[3]), "r"(b0), "r"(b1));
}

__device__ __forceinline__ void ldsm4(unsigned* r, uint32_t addr) {
    asm volatile("ldmatrix.sync.aligned.m8n8.x4.shared.b16 {%0,%1,%2,%3}, [%4];"
                 : "=r"(r[0]), "=r"(r[1]), "=r"(r[2]), "=r"(r[3]) : "r"(addr));
}
__device__ __forceinline__ void ldsm4t(unsigned* r, uint32_t addr) {
    asm volatile("ldmatrix.sync.aligned.m8n8.x4.trans.shared.b16 {%0,%1,%2,%3}, [%4];"
                 : "=r"(r[0]), "=r"(r[1]), "=r"(r[2]), "=r"(r[3]) : "r"(addr));
}

__device__ __forceinline__ void cp_async16(uint32_t dst, const void* src, int srcBytes) {
    asm volatile("cp.async.cg.shared.global [%0], [%1], 16, %2;\n"
                 :: "r"(dst), "l"(src), "r"(srcBytes));
}
#define CP_COMMIT() asm volatile("cp.async.commit_group;\n" ::: "memory")
#define CP_WAIT(n)  asm volatile("cp.async.wait_group %0;\n" :: "n"(n) : "memory")

// ---------------- fp32 -> fp16 conversion passes ----------------
__global__ void f2h_kernel(const float4* __restrict__ in,
                           __half2* __restrict__ out, int n4)
{
    const int i = blockIdx.x * blockDim.x + threadIdx.x;
    if (i < n4) {
        const float4 v = in[i];
        out[2 * i]     = __floats2half2_rn(v.x, v.y);
        out[2 * i + 1] = __floats2half2_rn(v.z, v.w);
    }
}

// in[R][C] fp32 -> out[C][R] fp16. R,C % 32 == 0. block (32,8).
__global__ void trTh_kernel(const float* __restrict__ in, __half* __restrict__ out,
                            int R, int Cc)
{
    __shared__ float t[32][33];
    const int c0 = blockIdx.x * 32, r0 = blockIdx.y * 32;
    const int tx = threadIdx.x, ty = threadIdx.y;
#pragma unroll
    for (int i = 0; i < 4; i++)
        t[ty + i * 8][tx] = in[(size_t)(r0 + ty + i * 8) * Cc + c0 + tx];
    __syncthreads();
#pragma unroll
    for (int i = 0; i < 4; i++)
        out[(size_t)(c0 + ty + i * 8) * R + r0 + tx] = __float2half_rn(t[tx][ty + i * 8]);
}

// ---------------- fp16 GEMM: C[M,N] = A[M,K] @ Bt[N,K]^T --------------------
// 128x128x64 tile, 256 thr (8 warps: wm 0..3 x wn 0..1), warp 32x64.
// 2-stage cp.async -> 73.7KB smem -> 2 CTAs/SM.
#define GASTRH   72
#define GTILE_B  (128 * GASTRH * 2)     // 18432 bytes per operand tile
#define GSTAGE_B (2 * GTILE_B)
#define GEMM_SMEM_BYTES (2 * GSTAGE_B)  // 73728

__global__ void __launch_bounds__(256, 2)
gemm_h(const __half* __restrict__ A, const __half* __restrict__ Bt,
       void* __restrict__ C, int M, int N, int K, int outHalf)
{
    extern __shared__ __half hsm[];
    const uint32_t sb = (uint32_t)__cvta_generic_to_shared(hsm);

    const int tid  = threadIdx.x;
    const int wid  = tid >> 5;
    const int lane = tid & 31;
    const int lr   = lane >> 2;
    const int lc   = lane & 3;
    const int g    = lane >> 3;
    const int l8   = lane & 7;
    const int wm   = wid & 3;
    const int wn   = wid >> 2;
    const int m0   = blockIdx.y * 128;
    const int n0   = blockIdx.x * 128;

    const uint32_t aBase = sb + (((wm * 32 + l8 + 8 * (g & 1)) * GASTRH + 8 * (g >> 1)) << 1);
    const uint32_t bBase = sb + GTILE_B +
                           (((wn * 64 + l8 + 8 * (g >> 1)) * GASTRH + 8 * (g & 1)) << 1);

    float acc[2][8][4];
#pragma unroll
    for (int i = 0; i < 2; i++)
#pragma unroll
        for (int j = 0; j < 8; j++)
#pragma unroll
            for (int k = 0; k < 4; k++) acc[i][j][k] = 0.f;

    auto loadTile = [&](int stage, int kt) {
        const uint32_t s0 = sb + (uint32_t)stage * GSTAGE_B;
        const int kb = kt * 64;
#pragma unroll
        for (int i = 0; i < 4; i++) {
            const int idx = tid + i * 256;
            const int row = idx >> 3, c8 = idx & 7;
            cp_async16(s0 + ((row * GASTRH + c8 * 8) << 1),
                       A + (size_t)(m0 + row) * K + kb + c8 * 8, 16);
        }
#pragma unroll
        for (int i = 0; i < 4; i++) {
            const int idx = tid + i * 256;
            const int n = idx >> 3, c8 = idx & 7;
            const int ng = n0 + n;
            const int ngc = ng < N ? ng : 0;
            cp_async16(s0 + GTILE_B + ((n * GASTRH + c8 * 8) << 1),
                       Bt + (size_t)ngc * K + kb + c8 * 8, ng < N ? 16 : 0);
        }
        CP_COMMIT();
    };

    const int T = K >> 6;
    loadTile(0, 0);
    if (T > 1) loadTile(1, 1);

    for (int it = 0; it < T; it++) {
        if (it + 1 < T) { CP_WAIT(1); } else { CP_WAIT(0); }
        __syncthreads();

        const uint32_t st = (uint32_t)(it & 1) * GSTAGE_B;
#pragma unroll
        for (int ks = 0; ks < 4; ks++) {
            unsigned a[2][4];
            ldsm4(a[0], aBase + st + ks * 32);
            ldsm4(a[1], aBase + st + ks * 32 + 16 * GASTRH * 2);
            unsigned b[8][2];
#pragma unroll
            for (int p = 0; p < 4; p++) {
                unsigned bb[4];
                ldsm4(bb, bBase + st + ks * 32 + p * (16 * GASTRH * 2));
                b[2 * p][0] = bb[0]; b[2 * p][1] = bb[1];
                b[2 * p + 1][0] = bb[2]; b[2 * p + 1][1] = bb[3];
            }
#pragma unroll
            for (int nt = 0; nt < 8; nt++) {
                mma16(acc[0][nt], a[0], b[nt][0], b[nt][1]);
                mma16(acc[1][nt], a[1], b[nt][0], b[nt][1]);
            }
        }
        if (it + 2 < T) {
            __syncthreads();                 // stage (it&1) free before refill
            loadTile(it & 1, it + 2);
        }
    }

#pragma unroll
    for (int mt = 0; mt < 2; mt++)
#pragma unroll
        for (int nt = 0; nt < 8; nt++) {
            const int row = m0 + wm * 32 + mt * 16 + lr;
            const int col = n0 + wn * 64 + nt * 8 + 2 * lc;
            if (col < N) {
                if (outHalf) {
                    *(__half2*)((__half*)C + (size_t)row * N + col) =
                        __floats2half2_rn(acc[mt][nt][0], acc[mt][nt][1]);
                    *(__half2*)((__half*)C + (size_t)(row + 8) * N + col) =
                        __floats2half2_rn(acc[mt][nt][2], acc[mt][nt][3]);
                } else {
                    *(float2*)((float*)C + (size_t)row * N + col) =
                        make_float2(acc[mt][nt][0], acc[mt][nt][1]);
                    *(float2*)((float*)C + (size_t)(row + 8) * N + col) =
                        make_float2(acc[mt][nt][2], acc[mt][nt][3]);
                }
            }
        }
}

// ---------------- prep: RMSNorm(c_kv), RoPE(k_rope), RoPE(q) -----------------
__global__ void prep_kernel(const float* __restrict__ w)
{
    const int row = blockIdx.x;
    const int s   = row % S_;
    const int tid = threadIdx.x;
    const __half* kva = g_kvah + (size_t)row * KVA_N;

    const float c0 = __half2float(kva[tid]);
    const float c1 = __half2float(kva[tid + 256]);
    float ss = c0 * c0 + c1 * c1;
#pragma unroll
    for (int o = 16; o > 0; o >>= 1) ss += __shfl_xor_sync(0xffffffffu, ss, o);
    __shared__ float red[8];
    if ((tid & 31) == 0) red[tid >> 5] = ss;
    __syncthreads();
    if (tid == 0) {
        float v = 0.f;
#pragma unroll
        for (int i = 0; i < 8; i++) v += red[i];
        red[0] = v;
    }
    __syncthreads();
    const float inv = rsqrtf(red[0] * (1.f / 512.f) + RMS_EPS);
    g_ckvh[(size_t)row * DKVL + tid]       = __float2half_rn(c0 * inv * w[tid]);
    g_ckvh[(size_t)row * DKVL + tid + 256] = __float2half_rn(c1 * inv * w[tid + 256]);

    if (tid < 32) {
        const float fr = expf(-(float)tid * ROPE_LC);
        const float t  = (float)s * fr;
        const float cs = cosf(t), sn = sinf(t);
        const float x1 = __half2float(kva[DKVL + 2 * tid]);
        const float x2 = __half2float(kva[DKVL + 2 * tid + 1]);
        *(__half2*)(g_krh + (size_t)row * DROPE + 2 * tid) =
            __floats2half2_rn(x1 * cs - x2 * sn, x2 * cs + x1 * sn);
    }

    for (int p = tid; p < NH * 32; p += 256) {
        const int h = p >> 5, i = p & 31;
        const float fr = expf(-(float)i * ROPE_LC);
        const float t  = (float)s * fr;
        const float cs = cosf(t), sn = sinf(t);
        __half2* qp = (__half2*)(g_qh + (size_t)row * HQ + h * DQKD + DNOPE + 2 * i);
        const __half2 v = *qp;
        const float x1 = __half2float(v.x), x2 = __half2float(v.y);
        *qp = __floats2half2_rn(x1 * cs - x2 * sn, x2 * cs + x1 * sn);
    }
}

// ---------------- fp16 tensor-core flash attention (BM=128, BN=64) -----------
#define QS_STRH 200
#define KS_STRH 200
#define VS_STRH 136
#define PS_STRH 72

#define QS_OFFH 0
#define KS_OFFH (128 * QS_STRH)            // 25600
#define VS_OFFH (KS_OFFH + 64 * KS_STRH)   // 38400
#define PS_OFFH (VS_OFFH + 64 * VS_STRH)   // 47104
#define ATT_HALVES (PS_OFFH + 128 * PS_STRH)
#define ATT_BYTES (ATT_HALVES * 2)         // 112640

__global__ void __launch_bounds__(256, 2)
attn_tc()
{
    extern __shared__ __half asm_[];
    __half* Ps = asm_ + PS_OFFH;
    const uint32_t sbase = (uint32_t)__cvta_generic_to_shared(asm_);
    const uint32_t sQ = sbase;
    const uint32_t sK = sbase + KS_OFFH * 2;
    const uint32_t sV = sbase + VS_OFFH * 2;
    const uint32_t sP = sbase + PS_OFFH * 2;

    // LPT scheduling: longest CTAs (largest qblk) launch first
    const int qblk = (S_ / 128 - 1) - blockIdx.x;
    const int h    = blockIdx.y;
    const int b    = blockIdx.z;
    const int tid  = threadIdx.x;
    const int w    = tid >> 5;
    const int lane = tid & 31;
    const int lr   = lane >> 2;
    const int lc   = lane & 3;
    const int g    = lane >> 3;
    const int l8   = lane & 7;
    const int w16  = w * 16;
    const int q0   = qblk * 128;
    const int bS   = b * S_;

    const float scale = 0.07216878364870323f; // 1/sqrt(192)

    const uint32_t qB = sQ + (((w16 + l8 + 8 * (g & 1)) * QS_STRH + 8 * (g >> 1)) << 1);
    const uint32_t kB = sK + (((l8 + 8 * (g >> 1)) * KS_STRH + 8 * (g & 1)) << 1);
    const uint32_t pA = sP + (((w16 + l8 + 8 * (g & 1)) * PS_STRH + 8 * (g >> 1)) << 1);
    const uint32_t vB = sV + (((l8 + 8 * (g & 1)) * VS_STRH + 8 * (g >> 1)) << 1);

#pragma unroll
    for (int i = 0; i < 12; i++) {
        const int idx = tid + i * 256;
        const int r = idx / 24, c8 = idx % 24;
        cp_async16(sQ + ((r * QS_STRH + c8 * 8) << 1),
                   g_qh + (size_t)(bS + q0 + r) * HQ + h * DQKD + c8 * 8, 16);
    }
    CP_COMMIT();

    float oacc[16][4];
#pragma unroll
    for (int i = 0; i < 16; i++)
#pragma unroll
        for (int j = 0; j < 4; j++) oacc[i][j] = 0.f;
    float m0v = -1e30f, m1v = -1e30f, l0 = 0.f, l1 = 0.f;

    const int row0g = q0 + w16 + lr;
    const int row1g = row0g + 8;
    const int lastNeeded = q0 + w16 + 15;

    CP_WAIT(0);
    __syncthreads();

    const int ktMax = 2 * qblk + 1;
    for (int kt = 0; kt <= ktMax; kt++) {
        const int k0 = kt * 64;

#pragma unroll
        for (int i = 0; i < 4; i++) {
            const int idx = tid + i * 256;
            const int j = idx >> 4, c8 = idx & 15;
            cp_async16(sK + ((j * KS_STRH + c8 * 8) << 1),
                       g_kvbh + (size_t)(bS + k0 + j) * HKV + h * 256 + c8 * 8, 16);
        }
#pragma unroll
        for (int i = 0; i < 2; i++) {
            const int idx = tid + i * 256;
            const int j = idx >> 3, c8 = idx & 7;
            cp_async16(sK + ((j * KS_STRH + 128 + c8 * 8) << 1),
                       g_krh + (size_t)(bS + k0 + j) * DROPE + c8 * 8, 16);
        }
#pragma unroll
        for (int i = 0; i < 4; i++) {
            const int idx = tid + i * 256;
            const int j = idx >> 4, c8 = idx & 15;
            cp_async16(sV + ((j * VS_STRH + c8 * 8) << 1),
                       g_kvbh + (size_t)(bS + k0 + j) * HKV + h * 256 + 128 + c8 * 8, 16);
        }
        CP_COMMIT();
        CP_WAIT(0);
        __syncthreads();

        if (k0 <= lastNeeded) {
            float sacc[8][4];
#pragma unroll
            for (int i = 0; i < 8; i++)
#pragma unroll
                for (int j = 0; j < 4; j++) sacc[i][j] = 0.f;

#pragma unroll
            for (int ks = 0; ks < 12; ks++) {
                unsigned a[4];
                ldsm4(a, qB + ks * 32);
#pragma unroll
                for (int p = 0; p < 4; p++) {
                    unsigned bb[4];
                    ldsm4(bb, kB + ks * 32 + p * (16 * KS_STRH * 2));
                    mma16(sacc[2 * p],     a, bb[0], bb[1]);
                    mma16(sacc[2 * p + 1], a, bb[2], bb[3]);
                }
            }

            const bool domask = (k0 + 63 > q0 + w16);
            float mt0 = -1e30f, mt1 = -1e30f;
#pragma unroll
            for (int nt = 0; nt < 8; nt++) {
                const int jb = k0 + nt * 8 + 2 * lc;
#pragma unroll
                for (int c = 0; c < 4; c++) {
                    float s = sacc[nt][c] * scale;
                    const int jg = jb + (c & 1);
                    const int rg = (c < 2) ? row0g : row1g;
                    if (domask && jg > rg) s = -1e30f;
                    sacc[nt][c] = s;
                    if (c < 2) mt0 = fmaxf(mt0, s); else mt1 = fmaxf(mt1, s);
                }
            }
            mt0 = fmaxf(mt0, __shfl_xor_sync(0xffffffffu, mt0, 1));
            mt0 = fmaxf(mt0, __shfl_xor_sync(0xffffffffu, mt0, 2));
            mt1 = fmaxf(mt1, __shfl_xor_sync(0xffffffffu, mt1, 1));
            mt1 = fmaxf(mt1, __shfl_xor_sync(0xffffffffu, mt1, 2));

            const float mn0 = fmaxf(m0v, mt0);
            const float mn1 = fmaxf(m1v, mt1);
            const float al0 = __expf(m0v - mn0);
            const float al1 = __expf(m1v - mn1);
            m0v = mn0; m1v = mn1;

            float rs0 = 0.f, rs1 = 0.f;
#pragma unroll
            for (int nt = 0; nt < 8; nt++) {
                const int jj = nt * 8 + 2 * lc;
                const float p0 = __expf(sacc[nt][0] - mn0);
                const float p1 = __expf(sacc[nt][1] - mn0);
                const float p2 = __expf(sacc[nt][2] - mn1);
                const float p3 = __expf(sacc[nt][3] - mn1);
                rs0 += p0 + p1; rs1 += p2 + p3;
                *(__half2*)(Ps + (w16 + lr) * PS_STRH + jj)     = __floats2half2_rn(p0, p1);
                *(__half2*)(Ps + (w16 + lr + 8) * PS_STRH + jj) = __floats2half2_rn(p2, p3);
            }
            rs0 += __shfl_xor_sync(0xffffffffu, rs0, 1);
            rs0 += __shfl_xor_sync(0xffffffffu, rs0, 2);
            rs1 += __shfl_xor_sync(0xffffffffu, rs1, 1);
            rs1 += __shfl_xor_sync(0xffffffffu, rs1, 2);
            l0 = l0 * al0 + rs0;
            l1 = l1 * al1 + rs1;

#pragma unroll
            for (int nt = 0; nt < 16; nt++) {
                oacc[nt][0] *= al0; oacc[nt][1] *= al0;
                oacc[nt][2] *= al1; oacc[nt][3] *= al1;
            }
            __syncwarp();

#pragma unroll
            for (int ks = 0; ks < 4; ks++) {
                unsigned a[4];
                ldsm4(a, pA + ks * 32);
#pragma unroll
                for (int p = 0; p < 8; p++) {
                    unsigned bb[4];
                    ldsm4t(bb, vB + ks * (16 * VS_STRH * 2) + p * 32);
                    mma16(oacc[2 * p],     a, bb[0], bb[1]);
                    mma16(oacc[2 * p + 1], a, bb[2], bb[3]);
                }
            }
        }
        __syncthreads();
    }

    const float inv0 = 1.f / l0;
    const float inv1 = 1.f / l1;
#pragma unroll
    for (int nt = 0; nt < 16; nt++) {
        const int col = h * DV + nt * 8 + 2 * lc;
        *(__half2*)(g_atth + (size_t)(bS + row0g) * (NH * DV) + col) =
            __floats2half2_rn(oacc[nt][0] * inv0, oacc[nt][1] * inv0);
        *(__half2*)(g_atth + (size_t)(bS + row1g) * (NH * DV) + col) =
            __floats2half2_rn(oacc[nt][2] * inv1, oacc[nt][3] * inv1);
    }
}

// ---------------- launch ----------------
extern "C" void kernel_launch(void* const* d_in, const int* in_sizes, int n_in,
                              void* d_out, int out_size)
{
    const float* x     = (const float*)d_in[0];
    const float* Wq    = (const float*)d_in[1];
    const float* Wkv_a = (const float*)d_in[2];
    const float* knw   = (const float*)d_in[3];
    const float* Wkv_b = (const float*)d_in[4];
    const float* Wo    = (const float*)d_in[5];
    float* out = (float*)d_out;

    static __half *p_qh, *p_kvah, *p_ckvh, *p_kvbh, *p_atth;
    static __half *p_xh, *p_wqTh, *p_wkvaTh, *p_wkvbTh, *p_woTh;
    static bool init = false;
    if (!init) {
        cudaGetSymbolAddress((void**)&p_qh,     g_qh);
        cudaGetSymbolAddress((void**)&p_kvah,   g_kvah);
        cudaGetSymbolAddress((void**)&p_ckvh,   g_ckvh);
        cudaGetSymbolAddress((void**)&p_kvbh,   g_kvbh);
        cudaGetSymbolAddress((void**)&p_atth,   g_atth);
        cudaGetSymbolAddress((void**)&p_xh,     g_xh);
        cudaGetSymbolAddress((void**)&p_wqTh,   g_wqTh);
        cudaGetSymbolAddress((void**)&p_wkvaTh, g_wkvaTh);
        cudaGetSymbolAddress((void**)&p_wkvbTh, g_wkvbTh);
        cudaGetSymbolAddress((void**)&p_woTh,   g_woTh);
        cudaFuncSetAttribute(attn_tc,
                             cudaFuncAttributeMaxDynamicSharedMemorySize, ATT_BYTES);
        cudaFuncSetAttribute(gemm_h,
                             cudaFuncAttributeMaxDynamicSharedMemorySize, GEMM_SMEM_BYTES);
        init = true;
    }

    {
        const int n4 = BS * DM / 4;
        f2h_kernel<<<(n4 + 255) / 256, 256>>>((const float4*)x, (__half2*)p_xh, n4);
    }
    const dim3 tb(32, 8);
    trTh_kernel<<<dim3(HQ / 32, DM / 32), tb>>>(Wq,    p_wqTh,   DM,   HQ);
    trTh_kernel<<<dim3(KVA_N / 32, DM / 32), tb>>>(Wkv_a, p_wkvaTh, DM,   KVA_N);
    trTh_kernel<<<dim3(HKV / 32, DKVL / 32), tb>>>(Wkv_b, p_wkvbTh, DKVL, HKV);
    trTh_kernel<<<dim3(DM / 32, DM / 32), tb>>>(Wo,    p_woTh,   DM,   DM);

    const dim3 blk(256);
    gemm_h<<<dim3(HQ / 128, BS / 128), blk, GEMM_SMEM_BYTES>>>(p_xh, p_wqTh, p_qh, BS, HQ, DM, 1);
    gemm_h<<<dim3((KVA_N + 127) / 128, BS / 128), blk, GEMM_SMEM_BYTES>>>(p_xh, p_wkvaTh, p_kvah, BS, KVA_N, DM, 1);
    prep_kernel<<<BS, 256>>>(knw);
    gemm_h<<<dim3(HKV / 128, BS / 128), blk, GEMM_SMEM_BYTES>>>(p_ckvh, p_wkvbTh, p_kvbh, BS, HKV, DKVL, 1);
    attn_tc<<<dim3(S_ / 128, NH, B_), 256, ATT_BYTES>>>();
    gemm_h<<<dim3(DM / 128, BS / 128), blk, GEMM_SMEM_BYTES>>>(p_atth, p_woTh, out, BS, DM, DM, 0);
}